// round 4
// baseline (speedup 1.0000x reference)
#include <cuda_runtime.h>
#include <cstdint>
#include <math_constants.h>

#define HEADS 8
#define HD 32
#define NTOK 49
#define DIM 256
#define BATCH 2048
#define NWIN 64

// scratch (allocation-free rule: device globals)
__device__ float g_qkv[(size_t)BATCH * NTOK * 3 * DIM];      // [B, N, 768]
__device__ float g_att[(size_t)BATCH * NTOK * DIM];          // [B, N, 256]
__device__ float g_comb[(size_t)NWIN * HEADS * NTOK * NTOK]; // [w][h][i][j]

__device__ __forceinline__ uint32_t f2tf32(float x) {
    uint32_t u;
    asm("cvt.rna.tf32.f32 %0, %1;" : "=r"(u) : "f"(x));
    return u;
}

__device__ __forceinline__ void mma_tf32(float* c, const uint32_t* a, const uint32_t* b) {
    asm volatile(
        "mma.sync.aligned.m16n8k8.row.col.f32.tf32.tf32.f32 "
        "{%0,%1,%2,%3}, {%4,%5,%6,%7}, {%8,%9}, {%0,%1,%2,%3};"
        : "+f"(c[0]), "+f"(c[1]), "+f"(c[2]), "+f"(c[3])
        : "r"(a[0]), "r"(a[1]), "r"(a[2]), "r"(a[3]), "r"(b[0]), "r"(b[1]));
}

__device__ __forceinline__ void split_tf32(float x, uint32_t& hi, uint32_t& lo) {
    hi = f2tf32(x);
    lo = f2tf32(x - __uint_as_float(hi));
}

// ---------------------------------------------------------------------------
// TF32 tensor-core GEMM, double-buffered: C[M,N] = A[M,K] @ B[K,N] + bias[N]
// BM=128, BN=128, BK=32, 256 threads (8 warps 2x4), warp tile 64x32
// dynamic smem: 2 * (128*36 + 32*136) * 4 = 71680 bytes
// ---------------------------------------------------------------------------
#define GEMM_SMEM_BYTES (2 * (128 * 36 + 32 * 136) * 4)

__global__ __launch_bounds__(256) void gemm_tf32_db(
    const float* __restrict__ A, const float* __restrict__ B,
    const float* __restrict__ bias, float* __restrict__ C,
    int M, int N, int K)
{
    constexpr int BM = 128, BN = 128, BK = 32;
    constexpr int ASTR = 36, BSTR = 136;

    extern __shared__ float sm[];
    float* Asm[2] = { sm, sm + BM * ASTR };
    float* Bsm[2] = { sm + 2 * BM * ASTR, sm + 2 * BM * ASTR + BK * BSTR };

    const int tid = threadIdx.x;
    const int wid = tid >> 5;
    const int lane = tid & 31;
    const int lr = lane >> 2;       // 0..7
    const int lc = lane & 3;        // 0..3
    const int wm = wid & 1;         // 2 tiles of 64 rows
    const int wn = wid >> 1;        // 4 tiles of 32 cols

    const int bm = blockIdx.y * BM;
    const int bn = blockIdx.x * BN;

    // global load mapping
    // A tile 128x32 = 1024 f4: idx = tid + 256*i (i<4): r = idx>>3, c4 = idx&7
    // B tile 32x128 = 1024 f4: idx = tid + 256*i (i<4): r = idx>>5, c4 = idx&31
    float4 apre[4], bpre[4];

    auto load_global = [&](int k0) {
        #pragma unroll
        for (int i = 0; i < 4; i++) {
            const int idx = tid + 256 * i;
            const int r = idx >> 3, c4 = idx & 7;
            apre[i] = *(const float4*)(A + (size_t)(bm + r) * K + k0 + c4 * 4);
        }
        #pragma unroll
        for (int i = 0; i < 4; i++) {
            const int idx = tid + 256 * i;
            const int r = idx >> 5, c4 = idx & 31;
            bpre[i] = *(const float4*)(B + (size_t)(k0 + r) * N + bn + c4 * 4);
        }
    };

    auto store_smem = [&](int s) {
        float* As = Asm[s];
        float* Bs = Bsm[s];
        #pragma unroll
        for (int i = 0; i < 4; i++) {
            const int idx = tid + 256 * i;
            const int r = idx >> 3, c4 = idx & 7;
            float4 v = apre[i];
            uint32_t* p = (uint32_t*)(As + r * ASTR + c4 * 4);
            p[0] = f2tf32(v.x); p[1] = f2tf32(v.y); p[2] = f2tf32(v.z); p[3] = f2tf32(v.w);
        }
        #pragma unroll
        for (int i = 0; i < 4; i++) {
            const int idx = tid + 256 * i;
            const int r = idx >> 5, c4 = idx & 31;
            float4 v = bpre[i];
            uint32_t* p = (uint32_t*)(Bs + r * BSTR + c4 * 4);
            p[0] = f2tf32(v.x); p[1] = f2tf32(v.y); p[2] = f2tf32(v.z); p[3] = f2tf32(v.w);
        }
    };

    float acc[4][4][4] = {};   // [mi][ni][frag]

    load_global(0);
    store_smem(0);
    const int niter = K / BK;

    for (int it = 0; it < niter; it++) {
        __syncthreads();
        const int s = it & 1;
        if (it + 1 < niter) load_global((it + 1) * BK);

        const float* As = Asm[s];
        const float* Bs = Bsm[s];

        #pragma unroll
        for (int ks = 0; ks < 4; ks++) {
            const int k = ks * 8;
            uint32_t afr[4][4];
            #pragma unroll
            for (int mi = 0; mi < 4; mi++) {
                const int r = wm * 64 + mi * 16;
                afr[mi][0] = __float_as_uint(As[(r + lr) * ASTR + k + lc]);
                afr[mi][1] = __float_as_uint(As[(r + 8 + lr) * ASTR + k + lc]);
                afr[mi][2] = __float_as_uint(As[(r + lr) * ASTR + k + 4 + lc]);
                afr[mi][3] = __float_as_uint(As[(r + 8 + lr) * ASTR + k + 4 + lc]);
            }
            uint32_t bfr[4][2];
            #pragma unroll
            for (int ni = 0; ni < 4; ni++) {
                const int c = wn * 32 + ni * 8 + lr;
                bfr[ni][0] = __float_as_uint(Bs[(k + lc) * BSTR + c]);
                bfr[ni][1] = __float_as_uint(Bs[(k + 4 + lc) * BSTR + c]);
            }
            #pragma unroll
            for (int mi = 0; mi < 4; mi++)
                #pragma unroll
                for (int ni = 0; ni < 4; ni++)
                    mma_tf32(acc[mi][ni], afr[mi], bfr[ni]);
        }

        if (it + 1 < niter) store_smem(1 - s);
    }

    // epilogue
    #pragma unroll
    for (int mi = 0; mi < 4; mi++) {
        #pragma unroll
        for (int ni = 0; ni < 4; ni++) {
            const int r0 = bm + wm * 64 + mi * 16 + lr;
            const int c0 = bn + wn * 32 + ni * 8 + lc * 2;
            float2 b01 = *(const float2*)(bias + c0);
            float2 v0 = make_float2(acc[mi][ni][0] + b01.x, acc[mi][ni][1] + b01.y);
            float2 v1 = make_float2(acc[mi][ni][2] + b01.x, acc[mi][ni][3] + b01.y);
            *(float2*)(C + (size_t)r0 * N + c0) = v0;
            *(float2*)(C + (size_t)(r0 + 8) * N + c0) = v1;
        }
    }
}

// ---------------------------------------------------------------------------
// comb[w][h][i][j] = mask[w][i][j] + bias_table[rel_index[i*49+j]][h]
// ---------------------------------------------------------------------------
__global__ __launch_bounds__(256) void comb_kernel(
    const float* __restrict__ mask, const float* __restrict__ bias_table,
    const int* __restrict__ rel_index, float* __restrict__ comb)
{
    const int total = NWIN * HEADS * NTOK * NTOK;
    int idx = blockIdx.x * 256 + threadIdx.x;
    if (idx < total) {
        const int ij = idx % (NTOK * NTOK);
        const int wh = idx / (NTOK * NTOK);
        const int h = wh & (HEADS - 1);
        const int w = wh >> 3;
        comb[idx] = mask[w * NTOK * NTOK + ij] + bias_table[rel_index[ij] * HEADS + h];
    }
}

// ---------------------------------------------------------------------------
// Tensor-core window attention: one block per (b, h). 4 warps, warp = m16 tile.
// ---------------------------------------------------------------------------
__global__ __launch_bounds__(128) void attn_mma_kernel(
    const float* __restrict__ qkv,       // [B, N, 768]
    const float* __restrict__ comb,      // [64][8][49][49]
    float* __restrict__ out)             // [B, N, 256]
{
    const int b = blockIdx.x;
    const int h = blockIdx.y;
    const int tid = threadIdx.x;
    const int wid = tid >> 5;
    const int lane = tid & 31;
    const int lr = lane >> 2;
    const int lc = lane & 3;

    __shared__ float Qf[64][36];
    __shared__ float Kf[56][36];
    __shared__ float Vf[56][40];
    __shared__ float Ss[64][60];

    const float scale = 0.17677669529663687f;
    const float* base = qkv + (size_t)b * NTOK * 3 * DIM + h * HD;

    for (int e = tid; e < NTOK * HD; e += 128) {
        const int n = e >> 5, d = e & 31;
        const float* row = base + (size_t)n * (3 * DIM) + d;
        Qf[n][d] = row[0] * scale;
        Kf[n][d] = row[DIM];
        Vf[n][d] = row[2 * DIM];
    }
    for (int e = tid; e < 7 * HD; e += 128) {
        Vf[NTOK + (e >> 5)][e & 31] = 0.f;
    }
    __syncthreads();

    const int mr = wid * 16;

    // ---- S = (Q*scale) @ K^T (3-term split tf32) ----
    {
        float sacc[7][4] = {};
        #pragma unroll
        for (int kt = 0; kt < 4; kt++) {
            const int k0 = kt * 8;
            float aq[4];
            aq[0] = Qf[mr + lr][k0 + lc];
            aq[1] = Qf[mr + 8 + lr][k0 + lc];
            aq[2] = Qf[mr + lr][k0 + 4 + lc];
            aq[3] = Qf[mr + 8 + lr][k0 + 4 + lc];
            uint32_t ah[4], al[4];
            #pragma unroll
            for (int t = 0; t < 4; t++) split_tf32(aq[t], ah[t], al[t]);

            #pragma unroll
            for (int nt = 0; nt < 7; nt++) {
                const int n0 = nt * 8;
                float b0 = Kf[n0 + lr][k0 + lc];
                float b1 = Kf[n0 + lr][k0 + 4 + lc];
                uint32_t bh[2], bl[2];
                split_tf32(b0, bh[0], bl[0]);
                split_tf32(b1, bh[1], bl[1]);
                mma_tf32(sacc[nt], ah, bh);
                mma_tf32(sacc[nt], al, bh);
                mma_tf32(sacc[nt], ah, bl);
            }
        }
        #pragma unroll
        for (int nt = 0; nt < 7; nt++) {
            const int c0 = nt * 8 + lc * 2;
            Ss[mr + lr][c0] = sacc[nt][0];
            Ss[mr + lr][c0 + 1] = sacc[nt][1];
            Ss[mr + 8 + lr][c0] = sacc[nt][2];
            Ss[mr + 8 + lr][c0 + 1] = sacc[nt][3];
        }
    }
    __syncthreads();

    // ---- softmax (warp-per-row), adds comb = bias + mask ----
    {
        const float* cb = comb + ((size_t)((b & (NWIN - 1)) * HEADS + h)) * (NTOK * NTOK);
        for (int i = wid; i < NTOK; i += 4) {
            const int j1 = lane + 32;
            float v0 = Ss[i][lane] + cb[i * NTOK + lane];
            float v1 = (j1 < NTOK) ? (Ss[i][j1] + cb[i * NTOK + j1]) : -CUDART_INF_F;
            float m = fmaxf(v0, v1);
            #pragma unroll
            for (int o = 16; o > 0; o >>= 1) m = fmaxf(m, __shfl_xor_sync(0xffffffffu, m, o));
            float e0 = __expf(v0 - m);
            float e1 = (j1 < NTOK) ? __expf(v1 - m) : 0.f;
            float s = e0 + e1;
            #pragma unroll
            for (int o = 16; o > 0; o >>= 1) s += __shfl_xor_sync(0xffffffffu, s, o);
            const float inv = 1.f / s;
            Ss[i][lane] = e0 * inv;
            if (j1 < 56) Ss[i][j1] = (j1 < NTOK) ? e1 * inv : 0.f;
        }
    }
    __syncthreads();

    // ---- O = P @ V (3-term split tf32) ----
    {
        float oacc[4][4] = {};
        #pragma unroll
        for (int kt = 0; kt < 7; kt++) {
            const int k0 = kt * 8;
            float ap[4];
            ap[0] = Ss[mr + lr][k0 + lc];
            ap[1] = Ss[mr + 8 + lr][k0 + lc];
            ap[2] = Ss[mr + lr][k0 + 4 + lc];
            ap[3] = Ss[mr + 8 + lr][k0 + 4 + lc];
            uint32_t ah[4], al[4];
            #pragma unroll
            for (int t = 0; t < 4; t++) split_tf32(ap[t], ah[t], al[t]);

            #pragma unroll
            for (int nt = 0; nt < 4; nt++) {
                const int n0 = nt * 8;
                float b0 = Vf[k0 + lc][n0 + lr];
                float b1 = Vf[k0 + 4 + lc][n0 + lr];
                uint32_t bh[2], bl[2];
                split_tf32(b0, bh[0], bl[0]);
                split_tf32(b1, bh[1], bl[1]);
                mma_tf32(oacc[nt], ah, bh);
                mma_tf32(oacc[nt], al, bh);
                mma_tf32(oacc[nt], ah, bl);
            }
        }

        const int r0 = mr + lr;
        const int r1 = mr + 8 + lr;
        #pragma unroll
        for (int nt = 0; nt < 4; nt++) {
            const int c0 = h * HD + nt * 8 + lc * 2;
            if (r0 < NTOK)
                *(float2*)(out + ((size_t)b * NTOK + r0) * DIM + c0) =
                    make_float2(oacc[nt][0], oacc[nt][1]);
            if (r1 < NTOK)
                *(float2*)(out + ((size_t)b * NTOK + r1) * DIM + c0) =
                    make_float2(oacc[nt][2], oacc[nt][3]);
        }
    }
}

// ---------------------------------------------------------------------------
extern "C" void kernel_launch(void* const* d_in, const int* in_sizes, int n_in,
                              void* d_out, int out_size)
{
    const float* x          = (const float*)d_in[0];
    const float* mask       = (const float*)d_in[1];
    const float* qkv_w      = (const float*)d_in[2];
    const float* qkv_b      = (const float*)d_in[3];
    const float* proj_w     = (const float*)d_in[4];
    const float* proj_b     = (const float*)d_in[5];
    const float* bias_table = (const float*)d_in[6];
    const int*   rel_index  = (const int*)d_in[7];
    float* out = (float*)d_out;

    float* qkv_buf = nullptr;
    float* att_buf = nullptr;
    float* comb_buf = nullptr;
    cudaGetSymbolAddress((void**)&qkv_buf, g_qkv);
    cudaGetSymbolAddress((void**)&att_buf, g_att);
    cudaGetSymbolAddress((void**)&comb_buf, g_comb);

    static bool attr_set = false;
    if (!attr_set) {
        cudaFuncSetAttribute(gemm_tf32_db,
                             cudaFuncAttributeMaxDynamicSharedMemorySize,
                             GEMM_SMEM_BYTES);
        attr_set = true;
    }

    const int M = BATCH * NTOK;   // 100352 = 128 * 784

    // 0) combined bias+mask table
    {
        const int total = NWIN * HEADS * NTOK * NTOK;
        comb_kernel<<<(total + 255) / 256, 256>>>(mask, bias_table, rel_index, comb_buf);
    }
    // 1) QKV GEMM: [M,256] @ [256,768] + b
    {
        dim3 grid(3 * DIM / 128, M / 128);
        gemm_tf32_db<<<grid, 256, GEMM_SMEM_BYTES>>>(x, qkv_w, qkv_b, qkv_buf,
                                                     M, 3 * DIM, DIM);
    }
    // 2) tensor-core window attention
    {
        dim3 grid(BATCH, HEADS);
        attn_mma_kernel<<<grid, 128>>>(qkv_buf, comb_buf, att_buf);
    }
    // 3) Proj GEMM: [M,256] @ [256,256] + b
    {
        dim3 grid(DIM / 128, M / 128);
        gemm_tf32_db<<<grid, 256, GEMM_SMEM_BYTES>>>(att_buf, proj_w, proj_b, out,
                                                     M, DIM, DIM);
    }
}

// round 5
// speedup vs baseline: 1.0544x; 1.0544x over previous
#include <cuda_runtime.h>
#include <cstdint>
#include <math_constants.h>

#define HEADS 8
#define HD 32
#define NTOK 49
#define DIM 256
#define BATCH 2048
#define NWIN 64

// scratch (allocation-free rule: device globals)
__device__ float g_qkv[(size_t)BATCH * NTOK * 3 * DIM];      // [B, N, 768]
__device__ float g_att[(size_t)BATCH * NTOK * DIM];          // [B, N, 256]
__device__ float g_comb[(size_t)NWIN * HEADS * NTOK * NTOK]; // [w][h][i][j]

__device__ __forceinline__ uint32_t f2tf32(float x) {
    uint32_t u;
    asm("cvt.rna.tf32.f32 %0, %1;" : "=r"(u) : "f"(x));
    return u;
}

__device__ __forceinline__ void mma_tf32(float* c, const uint32_t* a, const uint32_t* b) {
    asm volatile(
        "mma.sync.aligned.m16n8k8.row.col.f32.tf32.tf32.f32 "
        "{%0,%1,%2,%3}, {%4,%5,%6,%7}, {%8,%9}, {%0,%1,%2,%3};"
        : "+f"(c[0]), "+f"(c[1]), "+f"(c[2]), "+f"(c[3])
        : "r"(a[0]), "r"(a[1]), "r"(a[2]), "r"(a[3]), "r"(b[0]), "r"(b[1]));
}

__device__ __forceinline__ void split_tf32(float x, uint32_t& hi, uint32_t& lo) {
    hi = f2tf32(x);
    lo = f2tf32(x - __uint_as_float(hi));
}

// ---------------------------------------------------------------------------
// TF32 tensor-core GEMM (round-3 shape): C = A@B + bias
// BM=128, BN=64, BK=32, 256 threads (8 warps 4x2), warp tile 32x32
// launch_bounds(256,3): cap regs at ~85 for 3 CTAs/SM
// ---------------------------------------------------------------------------
__global__ __launch_bounds__(256, 3) void gemm_tf32_bias(
    const float* __restrict__ A, const float* __restrict__ B,
    const float* __restrict__ bias, float* __restrict__ C,
    int M, int N, int K)
{
    constexpr int BM = 128, BN = 64, BK = 32;
    constexpr int AS = 36;
    constexpr int BS = 72;
    __shared__ float As[BM][AS];
    __shared__ float Bs[BK][BS];

    const int tid = threadIdx.x;
    const int wid = tid >> 5;
    const int lane = tid & 31;
    const int lr = lane >> 2;
    const int lc = lane & 3;
    const int wm = wid & 3;
    const int wn = wid >> 2;

    const int bm = blockIdx.y * BM;
    const int bn = blockIdx.x * BN;

    float4 apre[4];
    float4 bpre[2];

    auto load_global = [&](int k0) {
        #pragma unroll
        for (int i = 0; i < 4; i++) {
            const int idx = tid + 256 * i;
            const int r = idx >> 3, c4 = idx & 7;
            apre[i] = *(const float4*)(A + (size_t)(bm + r) * K + k0 + c4 * 4);
        }
        #pragma unroll
        for (int i = 0; i < 2; i++) {
            const int idx = tid + 256 * i;
            const int r = idx >> 4, c4 = idx & 15;
            bpre[i] = *(const float4*)(B + (size_t)(k0 + r) * N + bn + c4 * 4);
        }
    };

    auto store_smem = [&]() {
        #pragma unroll
        for (int i = 0; i < 4; i++) {
            const int idx = tid + 256 * i;
            const int r = idx >> 3, c4 = idx & 7;
            float4 v = apre[i];
            uint32_t* p = (uint32_t*)&As[r][c4 * 4];
            p[0] = f2tf32(v.x); p[1] = f2tf32(v.y); p[2] = f2tf32(v.z); p[3] = f2tf32(v.w);
        }
        #pragma unroll
        for (int i = 0; i < 2; i++) {
            const int idx = tid + 256 * i;
            const int r = idx >> 4, c4 = idx & 15;
            float4 v = bpre[i];
            uint32_t* p = (uint32_t*)&Bs[r][c4 * 4];
            p[0] = f2tf32(v.x); p[1] = f2tf32(v.y); p[2] = f2tf32(v.z); p[3] = f2tf32(v.w);
        }
    };

    float acc[2][4][4] = {};

    load_global(0);
    const int niter = K / BK;
    for (int it = 0; it < niter; it++) {
        store_smem();
        __syncthreads();
        if (it + 1 < niter) load_global((it + 1) * BK);

        #pragma unroll
        for (int ks = 0; ks < 4; ks++) {
            const int k = ks * 8;
            uint32_t afr[2][4];
            #pragma unroll
            for (int mi = 0; mi < 2; mi++) {
                const int r = wm * 32 + mi * 16;
                afr[mi][0] = __float_as_uint(As[r + lr][k + lc]);
                afr[mi][1] = __float_as_uint(As[r + 8 + lr][k + lc]);
                afr[mi][2] = __float_as_uint(As[r + lr][k + 4 + lc]);
                afr[mi][3] = __float_as_uint(As[r + 8 + lr][k + 4 + lc]);
            }
            uint32_t bfr[4][2];
            #pragma unroll
            for (int ni = 0; ni < 4; ni++) {
                const int c = wn * 32 + ni * 8 + lr;
                bfr[ni][0] = __float_as_uint(Bs[k + lc][c]);
                bfr[ni][1] = __float_as_uint(Bs[k + 4 + lc][c]);
            }
            #pragma unroll
            for (int mi = 0; mi < 2; mi++)
                #pragma unroll
                for (int ni = 0; ni < 4; ni++)
                    mma_tf32(acc[mi][ni], afr[mi], bfr[ni]);
        }
        __syncthreads();
    }

    #pragma unroll
    for (int mi = 0; mi < 2; mi++) {
        #pragma unroll
        for (int ni = 0; ni < 4; ni++) {
            const int r0 = bm + wm * 32 + mi * 16 + lr;
            const int c0 = bn + wn * 32 + ni * 8 + lc * 2;
            float2 b01 = *(const float2*)(bias + c0);
            float2 v0 = make_float2(acc[mi][ni][0] + b01.x, acc[mi][ni][1] + b01.y);
            float2 v1 = make_float2(acc[mi][ni][2] + b01.x, acc[mi][ni][3] + b01.y);
            *(float2*)(C + (size_t)r0 * N + c0) = v0;
            *(float2*)(C + (size_t)(r0 + 8) * N + c0) = v1;
        }
    }
}

// ---------------------------------------------------------------------------
// comb[w][h][i][j] = mask[w][i][j] + bias_table[rel_index[i*49+j]][h]
// ---------------------------------------------------------------------------
__global__ __launch_bounds__(256) void comb_kernel(
    const float* __restrict__ mask, const float* __restrict__ bias_table,
    const int* __restrict__ rel_index, float* __restrict__ comb)
{
    const int total = NWIN * HEADS * NTOK * NTOK;
    int idx = blockIdx.x * 256 + threadIdx.x;
    if (idx < total) {
        const int ij = idx % (NTOK * NTOK);
        const int wh = idx / (NTOK * NTOK);
        const int h = wh & (HEADS - 1);
        const int w = wh >> 3;
        comb[idx] = mask[w * NTOK * NTOK + ij] + bias_table[rel_index[ij] * HEADS + h];
    }
}

// ---------------------------------------------------------------------------
// Tensor-core window attention, hoisted B-operand splits.
// One block per (b, h). 4 warps, warp = m16 tile. Dynamic smem.
// layout (floats):
//   Qf[64][36]  (2304)   q*scale fp32
//   Kh[56][36]  (2016)   K hi
//   Kl[56][36]  (2016)   K lo
//   Vh[56][40]  (2240)   V hi (pad rows zeroed)
//   Vl[56][40]  (2240)   V lo (pad rows zeroed)
//   Ss[64][60]  (3840)   S then P
// total 14656 floats = 58624 B
// ---------------------------------------------------------------------------
#define ATTN_SMEM_BYTES (14656 * 4)

__global__ __launch_bounds__(128) void attn_mma_kernel(
    const float* __restrict__ qkv,       // [B, N, 768]
    const float* __restrict__ comb,      // [64][8][49][49]
    float* __restrict__ out)             // [B, N, 256]
{
    extern __shared__ float smf[];
    float* Qf = smf;                 // [64][36]
    float* Kh = Qf + 2304;           // [56][36]
    float* Kl = Kh + 2016;           // [56][36]
    float* Vh = Kl + 2016;           // [56][40]
    float* Vl = Vh + 2240;           // [56][40]
    float* Ss = Vl + 2240;           // [64][60]

    const int b = blockIdx.x;
    const int h = blockIdx.y;
    const int tid = threadIdx.x;
    const int wid = tid >> 5;
    const int lane = tid & 31;
    const int lr = lane >> 2;
    const int lc = lane & 3;

    const float scale = 0.17677669529663687f;
    const float* base = qkv + (size_t)b * NTOK * 3 * DIM + h * HD;

    // load q/k/v; split k and v into hi/lo once
    for (int e = tid; e < NTOK * HD; e += 128) {
        const int n = e >> 5, d = e & 31;
        const float* row = base + (size_t)n * (3 * DIM) + d;
        Qf[n * 36 + d] = row[0] * scale;
        uint32_t khi, klo, vhi, vlo;
        split_tf32(row[DIM], khi, klo);
        split_tf32(row[2 * DIM], vhi, vlo);
        Kh[n * 36 + d] = __uint_as_float(khi);
        Kl[n * 36 + d] = __uint_as_float(klo);
        Vh[n * 40 + d] = __uint_as_float(vhi);
        Vl[n * 40 + d] = __uint_as_float(vlo);
    }
    // zero pads: Qf rows 49..63, Vh/Vl rows 49..55
    for (int e = tid; e < 15 * HD; e += 128)
        Qf[(NTOK + (e >> 5)) * 36 + (e & 31)] = 0.f;
    for (int e = tid; e < 7 * HD; e += 128) {
        const int r = NTOK + (e >> 5), d = e & 31;
        Vh[r * 40 + d] = 0.f;
        Vl[r * 40 + d] = 0.f;
    }
    __syncthreads();

    const int mr = wid * 16;

    // ---- S = (Q*scale) @ K^T (3-term split tf32, B splits hoisted) ----
    {
        float sacc[7][4] = {};
        #pragma unroll
        for (int kt = 0; kt < 4; kt++) {
            const int k0 = kt * 8;
            float aq[4];
            aq[0] = Qf[(mr + lr) * 36 + k0 + lc];
            aq[1] = Qf[(mr + 8 + lr) * 36 + k0 + lc];
            aq[2] = Qf[(mr + lr) * 36 + k0 + 4 + lc];
            aq[3] = Qf[(mr + 8 + lr) * 36 + k0 + 4 + lc];
            uint32_t ah[4], al[4];
            #pragma unroll
            for (int t = 0; t < 4; t++) split_tf32(aq[t], ah[t], al[t]);

            #pragma unroll
            for (int nt = 0; nt < 7; nt++) {
                const int n0 = nt * 8;
                uint32_t bh[2], bl[2];
                bh[0] = __float_as_uint(Kh[(n0 + lr) * 36 + k0 + lc]);
                bh[1] = __float_as_uint(Kh[(n0 + lr) * 36 + k0 + 4 + lc]);
                bl[0] = __float_as_uint(Kl[(n0 + lr) * 36 + k0 + lc]);
                bl[1] = __float_as_uint(Kl[(n0 + lr) * 36 + k0 + 4 + lc]);
                mma_tf32(sacc[nt], ah, bh);
                mma_tf32(sacc[nt], al, bh);
                mma_tf32(sacc[nt], ah, bl);
            }
        }
        #pragma unroll
        for (int nt = 0; nt < 7; nt++) {
            const int c0 = nt * 8 + lc * 2;
            Ss[(mr + lr) * 60 + c0] = sacc[nt][0];
            Ss[(mr + lr) * 60 + c0 + 1] = sacc[nt][1];
            Ss[(mr + 8 + lr) * 60 + c0] = sacc[nt][2];
            Ss[(mr + 8 + lr) * 60 + c0 + 1] = sacc[nt][3];
        }
    }
    __syncthreads();

    // ---- softmax (warp-per-row), adds comb = bias + mask ----
    {
        const float* cb = comb + ((size_t)((b & (NWIN - 1)) * HEADS + h)) * (NTOK * NTOK);
        for (int i = wid; i < NTOK; i += 4) {
            const int j1 = lane + 32;
            float v0 = Ss[i * 60 + lane] + cb[i * NTOK + lane];
            float v1 = (j1 < NTOK) ? (Ss[i * 60 + j1] + cb[i * NTOK + j1]) : -CUDART_INF_F;
            float m = fmaxf(v0, v1);
            #pragma unroll
            for (int o = 16; o > 0; o >>= 1) m = fmaxf(m, __shfl_xor_sync(0xffffffffu, m, o));
            float e0 = __expf(v0 - m);
            float e1 = (j1 < NTOK) ? __expf(v1 - m) : 0.f;
            float s = e0 + e1;
            #pragma unroll
            for (int o = 16; o > 0; o >>= 1) s += __shfl_xor_sync(0xffffffffu, s, o);
            const float inv = 1.f / s;
            Ss[i * 60 + lane] = e0 * inv;
            if (j1 < 56) Ss[i * 60 + j1] = (j1 < NTOK) ? e1 * inv : 0.f;
        }
    }
    __syncthreads();

    // ---- O = P @ V (3-term split tf32, B splits hoisted) ----
    {
        float oacc[4][4] = {};
        #pragma unroll
        for (int kt = 0; kt < 7; kt++) {
            const int k0 = kt * 8;
            float ap[4];
            ap[0] = Ss[(mr + lr) * 60 + k0 + lc];
            ap[1] = Ss[(mr + 8 + lr) * 60 + k0 + lc];
            ap[2] = Ss[(mr + lr) * 60 + k0 + 4 + lc];
            ap[3] = Ss[(mr + 8 + lr) * 60 + k0 + 4 + lc];
            uint32_t ah[4], al[4];
            #pragma unroll
            for (int t = 0; t < 4; t++) split_tf32(ap[t], ah[t], al[t]);

            #pragma unroll
            for (int nt = 0; nt < 4; nt++) {
                const int n0 = nt * 8;
                uint32_t bh[2], bl[2];
                bh[0] = __float_as_uint(Vh[(k0 + lc) * 40 + n0 + lr]);
                bh[1] = __float_as_uint(Vh[(k0 + 4 + lc) * 40 + n0 + lr]);
                bl[0] = __float_as_uint(Vl[(k0 + lc) * 40 + n0 + lr]);
                bl[1] = __float_as_uint(Vl[(k0 + 4 + lc) * 40 + n0 + lr]);
                mma_tf32(oacc[nt], ah, bh);
                mma_tf32(oacc[nt], al, bh);
                mma_tf32(oacc[nt], ah, bl);
            }
        }

        const int r0 = mr + lr;
        const int r1 = mr + 8 + lr;
        #pragma unroll
        for (int nt = 0; nt < 4; nt++) {
            const int c0 = h * HD + nt * 8 + lc * 2;
            if (r0 < NTOK)
                *(float2*)(out + ((size_t)b * NTOK + r0) * DIM + c0) =
                    make_float2(oacc[nt][0], oacc[nt][1]);
            if (r1 < NTOK)
                *(float2*)(out + ((size_t)b * NTOK + r1) * DIM + c0) =
                    make_float2(oacc[nt][2], oacc[nt][3]);
        }
    }
}

// ---------------------------------------------------------------------------
extern "C" void kernel_launch(void* const* d_in, const int* in_sizes, int n_in,
                              void* d_out, int out_size)
{
    const float* x          = (const float*)d_in[0];
    const float* mask       = (const float*)d_in[1];
    const float* qkv_w      = (const float*)d_in[2];
    const float* qkv_b      = (const float*)d_in[3];
    const float* proj_w     = (const float*)d_in[4];
    const float* proj_b     = (const float*)d_in[5];
    const float* bias_table = (const float*)d_in[6];
    const int*   rel_index  = (const int*)d_in[7];
    float* out = (float*)d_out;

    float* qkv_buf = nullptr;
    float* att_buf = nullptr;
    float* comb_buf = nullptr;
    cudaGetSymbolAddress((void**)&qkv_buf, g_qkv);
    cudaGetSymbolAddress((void**)&att_buf, g_att);
    cudaGetSymbolAddress((void**)&comb_buf, g_comb);

    static bool attr_set = false;
    if (!attr_set) {
        cudaFuncSetAttribute(attn_mma_kernel,
                             cudaFuncAttributeMaxDynamicSharedMemorySize,
                             ATTN_SMEM_BYTES);
        attr_set = true;
    }

    const int M = BATCH * NTOK;   // 100352 = 128 * 784

    // 0) combined bias+mask table
    {
        const int total = NWIN * HEADS * NTOK * NTOK;
        comb_kernel<<<(total + 255) / 256, 256>>>(mask, bias_table, rel_index, comb_buf);
    }
    // 1) QKV GEMM: [M,256] @ [256,768] + b
    {
        dim3 grid(3 * DIM / 64, M / 128);
        gemm_tf32_bias<<<grid, 256>>>(x, qkv_w, qkv_b, qkv_buf, M, 3 * DIM, DIM);
    }
    // 2) tensor-core window attention
    {
        dim3 grid(BATCH, HEADS);
        attn_mma_kernel<<<grid, 128, ATTN_SMEM_BYTES>>>(qkv_buf, comb_buf, att_buf);
    }
    // 3) Proj GEMM: [M,256] @ [256,256] + b
    {
        dim3 grid(DIM / 64, M / 128);
        gemm_tf32_bias<<<grid, 256>>>(att_buf, proj_w, proj_b, out, M, DIM, DIM);
    }
}

// round 6
// speedup vs baseline: 1.3371x; 1.2681x over previous
#include <cuda_runtime.h>
#include <cuda_bf16.h>
#include <cstdint>
#include <math_constants.h>

#define HEADS 8
#define HD 32
#define NTOK 49
#define DIM 256
#define BATCH 2048
#define NWIN 64

// scratch (allocation-free rule: device globals)
__device__ float g_qkv[(size_t)BATCH * NTOK * 3 * DIM];      // [B, N, 768]
__device__ float g_att[(size_t)BATCH * NTOK * DIM];          // [B, N, 256]
__device__ float g_comb[(size_t)NWIN * HEADS * NTOK * NTOK]; // [w][h][i][j]

__device__ __forceinline__ uint32_t f2tf32(float x) {
    uint32_t u;
    asm("cvt.rna.tf32.f32 %0, %1;" : "=r"(u) : "f"(x));
    return u;
}

__device__ __forceinline__ void mma_tf32(float* c, const uint32_t* a, const uint32_t* b) {
    asm volatile(
        "mma.sync.aligned.m16n8k8.row.col.f32.tf32.tf32.f32 "
        "{%0,%1,%2,%3}, {%4,%5,%6,%7}, {%8,%9}, {%0,%1,%2,%3};"
        : "+f"(c[0]), "+f"(c[1]), "+f"(c[2]), "+f"(c[3])
        : "r"(a[0]), "r"(a[1]), "r"(a[2]), "r"(a[3]), "r"(b[0]), "r"(b[1]));
}

__device__ __forceinline__ void mma_bf16(float* c, const uint32_t* a, const uint32_t* b) {
    asm volatile(
        "mma.sync.aligned.m16n8k16.row.col.f32.bf16.bf16.f32 "
        "{%0,%1,%2,%3}, {%4,%5,%6,%7}, {%8,%9}, {%0,%1,%2,%3};"
        : "+f"(c[0]), "+f"(c[1]), "+f"(c[2]), "+f"(c[3])
        : "r"(a[0]), "r"(a[1]), "r"(a[2]), "r"(a[3]), "r"(b[0]), "r"(b[1]));
}

// pack two floats into hi bf16x2 + lo bf16x2 (2-way split)
__device__ __forceinline__ void split_pack_bf16(float x, float y,
                                                uint32_t& hi, uint32_t& lo) {
    __nv_bfloat16 hx = __float2bfloat16(x);
    __nv_bfloat16 hy = __float2bfloat16(y);
    __nv_bfloat16 lx = __float2bfloat16(x - __bfloat162float(hx));
    __nv_bfloat16 ly = __float2bfloat16(y - __bfloat162float(hy));
    __nv_bfloat162 h; h.x = hx; h.y = hy;
    __nv_bfloat162 l; l.x = lx; l.y = ly;
    hi = *(uint32_t*)&h;
    lo = *(uint32_t*)&l;
}

// ---------------------------------------------------------------------------
// TF32 tensor-core GEMM (round-3, known-good): C = A@B + bias
// BM=128, BN=64, BK=32, 256 threads (8 warps 4x2), warp tile 32x32
// ---------------------------------------------------------------------------
__global__ __launch_bounds__(256) void gemm_tf32_bias(
    const float* __restrict__ A, const float* __restrict__ B,
    const float* __restrict__ bias, float* __restrict__ C,
    int M, int N, int K)
{
    constexpr int BM = 128, BN = 64, BK = 32;
    constexpr int AS = 36;
    constexpr int BS = 72;
    __shared__ float As[BM][AS];
    __shared__ float Bs[BK][BS];

    const int tid = threadIdx.x;
    const int wid = tid >> 5;
    const int lane = tid & 31;
    const int lr = lane >> 2;
    const int lc = lane & 3;
    const int wm = wid & 3;
    const int wn = wid >> 2;

    const int bm = blockIdx.y * BM;
    const int bn = blockIdx.x * BN;

    float4 apre[4];
    float4 bpre[2];

    auto load_global = [&](int k0) {
        #pragma unroll
        for (int i = 0; i < 4; i++) {
            const int idx = tid + 256 * i;
            const int r = idx >> 3, c4 = idx & 7;
            apre[i] = *(const float4*)(A + (size_t)(bm + r) * K + k0 + c4 * 4);
        }
        #pragma unroll
        for (int i = 0; i < 2; i++) {
            const int idx = tid + 256 * i;
            const int r = idx >> 4, c4 = idx & 15;
            bpre[i] = *(const float4*)(B + (size_t)(k0 + r) * N + bn + c4 * 4);
        }
    };

    auto store_smem = [&]() {
        #pragma unroll
        for (int i = 0; i < 4; i++) {
            const int idx = tid + 256 * i;
            const int r = idx >> 3, c4 = idx & 7;
            float4 v = apre[i];
            uint32_t* p = (uint32_t*)&As[r][c4 * 4];
            p[0] = f2tf32(v.x); p[1] = f2tf32(v.y); p[2] = f2tf32(v.z); p[3] = f2tf32(v.w);
        }
        #pragma unroll
        for (int i = 0; i < 2; i++) {
            const int idx = tid + 256 * i;
            const int r = idx >> 4, c4 = idx & 15;
            float4 v = bpre[i];
            uint32_t* p = (uint32_t*)&Bs[r][c4 * 4];
            p[0] = f2tf32(v.x); p[1] = f2tf32(v.y); p[2] = f2tf32(v.z); p[3] = f2tf32(v.w);
        }
    };

    float acc[2][4][4] = {};

    load_global(0);
    const int niter = K / BK;
    for (int it = 0; it < niter; it++) {
        store_smem();
        __syncthreads();
        if (it + 1 < niter) load_global((it + 1) * BK);

        #pragma unroll
        for (int ks = 0; ks < 4; ks++) {
            const int k = ks * 8;
            uint32_t afr[2][4];
            #pragma unroll
            for (int mi = 0; mi < 2; mi++) {
                const int r = wm * 32 + mi * 16;
                afr[mi][0] = __float_as_uint(As[r + lr][k + lc]);
                afr[mi][1] = __float_as_uint(As[r + 8 + lr][k + lc]);
                afr[mi][2] = __float_as_uint(As[r + lr][k + 4 + lc]);
                afr[mi][3] = __float_as_uint(As[r + 8 + lr][k + 4 + lc]);
            }
            uint32_t bfr[4][2];
            #pragma unroll
            for (int ni = 0; ni < 4; ni++) {
                const int c = wn * 32 + ni * 8 + lr;
                bfr[ni][0] = __float_as_uint(Bs[k + lc][c]);
                bfr[ni][1] = __float_as_uint(Bs[k + 4 + lc][c]);
            }
            #pragma unroll
            for (int mi = 0; mi < 2; mi++)
                #pragma unroll
                for (int ni = 0; ni < 4; ni++)
                    mma_tf32(acc[mi][ni], afr[mi], bfr[ni]);
        }
        __syncthreads();
    }

    #pragma unroll
    for (int mi = 0; mi < 2; mi++) {
        #pragma unroll
        for (int ni = 0; ni < 4; ni++) {
            const int r0 = bm + wm * 32 + mi * 16 + lr;
            const int c0 = bn + wn * 32 + ni * 8 + lc * 2;
            float2 b01 = *(const float2*)(bias + c0);
            float2 v0 = make_float2(acc[mi][ni][0] + b01.x, acc[mi][ni][1] + b01.y);
            float2 v1 = make_float2(acc[mi][ni][2] + b01.x, acc[mi][ni][3] + b01.y);
            *(float2*)(C + (size_t)r0 * N + c0) = v0;
            *(float2*)(C + (size_t)(r0 + 8) * N + c0) = v1;
        }
    }
}

// ---------------------------------------------------------------------------
// comb[w][h][i][j] = mask[w][i][j] + bias_table[rel_index[i*49+j]][h]
// ---------------------------------------------------------------------------
__global__ __launch_bounds__(256) void comb_kernel(
    const float* __restrict__ mask, const float* __restrict__ bias_table,
    const int* __restrict__ rel_index, float* __restrict__ comb)
{
    const int total = NWIN * HEADS * NTOK * NTOK;
    int idx = blockIdx.x * 256 + threadIdx.x;
    if (idx < total) {
        const int ij = idx % (NTOK * NTOK);
        const int wh = idx / (NTOK * NTOK);
        const int h = wh & (HEADS - 1);
        const int w = wh >> 3;
        comb[idx] = mask[w * NTOK * NTOK + ij] + bias_table[rel_index[ij] * HEADS + h];
    }
}

// ---------------------------------------------------------------------------
// bf16 split-2, 3-term tensor-core window attention.
// One block per (b, h). 4 warps, warp = m16 row-tile.
//
// Dynamic smem layout (32-bit words):
//   [0,     1280)  Qh  : 64 rows x 20 w (bf16x2 pairs, stride 20)  } S phase
//   [1280,  2560)  Ql                                              }
//   [0,     2304)  Ph  : 64 rows x 36 w (stride 36)   } PV phase (reuses Q region)
//   [2304,  4608)  Pl                                 }
//   [4608,  5728)  Kh  : 56 rows x 20 w
//   [5728,  6848)  Kl
//   [6848,  8000)  Vth : 32 rows x 36 w (V transposed: [d][j])
//   [8000,  9152)  Vtl
//   [9152, 12992)  Ss  : 64 rows x 60 fp32
// total 12992 words = 51968 bytes
// ---------------------------------------------------------------------------
#define ATTN_SMEM_BYTES (12992 * 4)

__global__ __launch_bounds__(128) void attn_bf16_kernel(
    const float* __restrict__ qkv,       // [B, N, 768]
    const float* __restrict__ comb,      // [64][8][49][49]
    float* __restrict__ out)             // [B, N, 256]
{
    extern __shared__ __align__(16) uint32_t sw[];
    uint32_t* Qh  = sw;
    uint32_t* Ql  = sw + 1280;
    uint32_t* Ph  = sw;            // overlays Q after S phase
    uint32_t* Pl  = sw + 2304;
    uint32_t* Kh  = sw + 4608;
    uint32_t* Kl  = sw + 5728;
    uint32_t* Vth = sw + 6848;
    uint32_t* Vtl = sw + 8000;
    float*    Ss  = (float*)(sw + 9152);

    const int b = blockIdx.x;
    const int h = blockIdx.y;
    const int tid = threadIdx.x;
    const int wid = tid >> 5;
    const int lane = tid & 31;
    const int lr = lane >> 2;
    const int lc = lane & 3;

    const float scale = 0.17677669529663687f;   // 32^-0.5
    const float* base = qkv + (size_t)b * NTOK * 3 * DIM + h * HD;

    // zero V-transpose pad halves j = 49..63 (both planes): 0 * NaN guard
    {
        __nv_bfloat16* vhH = (__nv_bfloat16*)Vth;
        __nv_bfloat16* vlH = (__nv_bfloat16*)Vtl;
        for (int e = tid; e < HD * 15; e += 128) {
            const int d = e / 15;
            const int j = NTOK + (e % 15);    // 49..63
            vhH[d * 72 + j] = __float2bfloat16(0.f);
            vlH[d * 72 + j] = __float2bfloat16(0.f);
        }
    }

    // load q/k/v: one thread per (token, dim-pair); split into bf16 hi/lo
    {
        __nv_bfloat16* vhH = (__nv_bfloat16*)Vth;
        __nv_bfloat16* vlH = (__nv_bfloat16*)Vtl;
        for (int pe = tid; pe < NTOK * (HD / 2); pe += 128) {
            const int n = pe >> 4;
            const int dp = pe & 15;          // word (pair) index, d = 2*dp
            const int d = dp * 2;
            const float* row = base + (size_t)n * (3 * DIM) + d;
            float2 q2 = *(const float2*)(row);
            float2 k2 = *(const float2*)(row + DIM);
            float2 v2 = *(const float2*)(row + 2 * DIM);
            q2.x *= scale; q2.y *= scale;

            uint32_t hi, lo;
            split_pack_bf16(q2.x, q2.y, hi, lo);
            Qh[n * 20 + dp] = hi;
            Ql[n * 20 + dp] = lo;
            split_pack_bf16(k2.x, k2.y, hi, lo);
            Kh[n * 20 + dp] = hi;
            Kl[n * 20 + dp] = lo;

            // V transposed: Vt[d][j=n], k-contiguous for B fragments
            __nv_bfloat16 vh0 = __float2bfloat16(v2.x);
            __nv_bfloat16 vh1 = __float2bfloat16(v2.y);
            __nv_bfloat16 vl0 = __float2bfloat16(v2.x - __bfloat162float(vh0));
            __nv_bfloat16 vl1 = __float2bfloat16(v2.y - __bfloat162float(vh1));
            vhH[d * 72 + n] = vh0;
            vhH[(d + 1) * 72 + n] = vh1;
            vlH[d * 72 + n] = vl0;
            vlH[(d + 1) * 72 + n] = vl1;
        }
    }
    __syncthreads();

    const int mr = wid * 16;

    // ---- S = (Q*scale) @ K^T : bf16 split-2, 3-term, k16 x 2 steps ----
    {
        float sacc[7][4] = {};
        #pragma unroll
        for (int kt = 0; kt < 2; kt++) {
            const int kw = kt * 8;
            uint32_t ah[4], al[4];
            ah[0] = Qh[(mr + lr) * 20 + kw + lc];
            ah[1] = Qh[(mr + 8 + lr) * 20 + kw + lc];
            ah[2] = Qh[(mr + lr) * 20 + kw + 4 + lc];
            ah[3] = Qh[(mr + 8 + lr) * 20 + kw + 4 + lc];
            al[0] = Ql[(mr + lr) * 20 + kw + lc];
            al[1] = Ql[(mr + 8 + lr) * 20 + kw + lc];
            al[2] = Ql[(mr + lr) * 20 + kw + 4 + lc];
            al[3] = Ql[(mr + 8 + lr) * 20 + kw + 4 + lc];

            #pragma unroll
            for (int nt = 0; nt < 7; nt++) {
                const int n0 = nt * 8;
                uint32_t bh[2], bl[2];
                bh[0] = Kh[(n0 + lr) * 20 + kw + lc];
                bh[1] = Kh[(n0 + lr) * 20 + kw + 4 + lc];
                bl[0] = Kl[(n0 + lr) * 20 + kw + lc];
                bl[1] = Kl[(n0 + lr) * 20 + kw + 4 + lc];
                mma_bf16(sacc[nt], ah, bh);
                mma_bf16(sacc[nt], al, bh);
                mma_bf16(sacc[nt], ah, bl);
            }
        }
        #pragma unroll
        for (int nt = 0; nt < 7; nt++) {
            const int c0 = nt * 8 + lc * 2;
            Ss[(mr + lr) * 60 + c0] = sacc[nt][0];
            Ss[(mr + lr) * 60 + c0 + 1] = sacc[nt][1];
            Ss[(mr + 8 + lr) * 60 + c0] = sacc[nt][2];
            Ss[(mr + 8 + lr) * 60 + c0 + 1] = sacc[nt][3];
        }
    }
    __syncthreads();

    // ---- softmax (warp-per-row) + bf16 split of P into Ph/Pl (all 64 cols) ----
    {
        const float* cb = comb + ((size_t)((b & (NWIN - 1)) * HEADS + h)) * (NTOK * NTOK);
        __nv_bfloat16* phH = (__nv_bfloat16*)Ph;
        __nv_bfloat16* plH = (__nv_bfloat16*)Pl;
        for (int i = wid; i < NTOK; i += 4) {
            const int j1 = lane + 32;
            float v0 = Ss[i * 60 + lane] + cb[i * NTOK + lane];
            float v1 = (j1 < NTOK) ? (Ss[i * 60 + j1] + cb[i * NTOK + j1]) : -CUDART_INF_F;
            float m = fmaxf(v0, v1);
            #pragma unroll
            for (int o = 16; o > 0; o >>= 1) m = fmaxf(m, __shfl_xor_sync(0xffffffffu, m, o));
            float e0 = __expf(v0 - m);
            float e1 = (j1 < NTOK) ? __expf(v1 - m) : 0.f;
            float s = e0 + e1;
            #pragma unroll
            for (int o = 16; o > 0; o >>= 1) s += __shfl_xor_sync(0xffffffffu, s, o);
            const float inv = 1.f / s;
            float p0 = e0 * inv;
            float p1 = e1 * inv;    // 0 for j1 >= 49

            __nv_bfloat16 h0 = __float2bfloat16(p0);
            __nv_bfloat16 l0 = __float2bfloat16(p0 - __bfloat162float(h0));
            __nv_bfloat16 h1 = __float2bfloat16(p1);
            __nv_bfloat16 l1 = __float2bfloat16(p1 - __bfloat162float(h1));
            phH[i * 72 + lane] = h0;
            phH[i * 72 + j1]   = h1;
            plH[i * 72 + lane] = l0;
            plH[i * 72 + j1]   = l1;
        }
    }
    __syncthreads();

    // ---- O = P @ V : bf16 split-2, 3-term, k16 x 4 steps (j padded to 64) ----
    {
        float oacc[4][4] = {};
        #pragma unroll
        for (int kt = 0; kt < 4; kt++) {
            const int kw = kt * 8;
            uint32_t ah[4], al[4];
            ah[0] = Ph[(mr + lr) * 36 + kw + lc];
            ah[1] = Ph[(mr + 8 + lr) * 36 + kw + lc];
            ah[2] = Ph[(mr + lr) * 36 + kw + 4 + lc];
            ah[3] = Ph[(mr + 8 + lr) * 36 + kw + 4 + lc];
            al[0] = Pl[(mr + lr) * 36 + kw + lc];
            al[1] = Pl[(mr + 8 + lr) * 36 + kw + lc];
            al[2] = Pl[(mr + lr) * 36 + kw + 4 + lc];
            al[3] = Pl[(mr + 8 + lr) * 36 + kw + 4 + lc];

            #pragma unroll
            for (int nt = 0; nt < 4; nt++) {
                const int n0 = nt * 8;
                uint32_t bh[2], bl[2];
                bh[0] = Vth[(n0 + lr) * 36 + kw + lc];
                bh[1] = Vth[(n0 + lr) * 36 + kw + 4 + lc];
                bl[0] = Vtl[(n0 + lr) * 36 + kw + lc];
                bl[1] = Vtl[(n0 + lr) * 36 + kw + 4 + lc];
                mma_bf16(oacc[nt], ah, bh);
                mma_bf16(oacc[nt], al, bh);
                mma_bf16(oacc[nt], ah, bl);
            }
        }

        const int r0 = mr + lr;
        const int r1 = mr + 8 + lr;
        #pragma unroll
        for (int nt = 0; nt < 4; nt++) {
            const int c0 = h * HD + nt * 8 + lc * 2;
            if (r0 < NTOK)
                *(float2*)(out + ((size_t)b * NTOK + r0) * DIM + c0) =
                    make_float2(oacc[nt][0], oacc[nt][1]);
            if (r1 < NTOK)
                *(float2*)(out + ((size_t)b * NTOK + r1) * DIM + c0) =
                    make_float2(oacc[nt][2], oacc[nt][3]);
        }
    }
}

// ---------------------------------------------------------------------------
extern "C" void kernel_launch(void* const* d_in, const int* in_sizes, int n_in,
                              void* d_out, int out_size)
{
    const float* x          = (const float*)d_in[0];
    const float* mask       = (const float*)d_in[1];
    const float* qkv_w      = (const float*)d_in[2];
    const float* qkv_b      = (const float*)d_in[3];
    const float* proj_w     = (const float*)d_in[4];
    const float* proj_b     = (const float*)d_in[5];
    const float* bias_table = (const float*)d_in[6];
    const int*   rel_index  = (const int*)d_in[7];
    float* out = (float*)d_out;

    float* qkv_buf = nullptr;
    float* att_buf = nullptr;
    float* comb_buf = nullptr;
    cudaGetSymbolAddress((void**)&qkv_buf, g_qkv);
    cudaGetSymbolAddress((void**)&att_buf, g_att);
    cudaGetSymbolAddress((void**)&comb_buf, g_comb);

    static bool attr_set = false;
    if (!attr_set) {
        cudaFuncSetAttribute(attn_bf16_kernel,
                             cudaFuncAttributeMaxDynamicSharedMemorySize,
                             ATTN_SMEM_BYTES);
        attr_set = true;
    }

    const int M = BATCH * NTOK;   // 100352 = 128 * 784

    // 0) combined bias+mask table
    {
        const int total = NWIN * HEADS * NTOK * NTOK;
        comb_kernel<<<(total + 255) / 256, 256>>>(mask, bias_table, rel_index, comb_buf);
    }
    // 1) QKV GEMM: [M,256] @ [256,768] + b
    {
        dim3 grid(3 * DIM / 64, M / 128);
        gemm_tf32_bias<<<grid, 256>>>(x, qkv_w, qkv_b, qkv_buf, M, 3 * DIM, DIM);
    }
    // 2) bf16 tensor-core window attention
    {
        dim3 grid(BATCH, HEADS);
        attn_bf16_kernel<<<grid, 128, ATTN_SMEM_BYTES>>>(qkv_buf, comb_buf, att_buf);
    }
    // 3) Proj GEMM: [M,256] @ [256,256] + b
    {
        dim3 grid(DIM / 64, M / 128);
        gemm_tf32_bias<<<grid, 256>>>(att_buf, proj_w, proj_b, out, M, DIM, DIM);
    }
}

// round 7
// speedup vs baseline: 1.4498x; 1.0842x over previous
#include <cuda_runtime.h>
#include <cuda_bf16.h>
#include <cstdint>
#include <math_constants.h>

#define HEADS 8
#define HD 32
#define NTOK 49
#define DIM 256
#define BATCH 2048
#define NWIN 64

// scratch (allocation-free rule: device globals)
__device__ float g_xt[(size_t)BATCH * NTOK * DIM];           // tf32(x)
__device__ float g_qkv[(size_t)BATCH * NTOK * 3 * DIM];      // [B, N, 768]
__device__ float g_ao[(size_t)BATCH * NTOK * DIM];           // attention out (tf32-rounded)
__device__ float g_wq[DIM * 3 * DIM];                        // tf32(qkv_w)
__device__ float g_wp[DIM * DIM];                            // tf32(proj_w)
__device__ float g_comb[(size_t)NWIN * HEADS * NTOK * NTOK]; // [w][h][i][j]

__device__ __forceinline__ uint32_t f2tf32(float x) {
    uint32_t u;
    asm("cvt.rna.tf32.f32 %0, %1;" : "=r"(u) : "f"(x));
    return u;
}

__device__ __forceinline__ void mma_tf32(float* c, const uint32_t* a, const uint32_t* b) {
    asm volatile(
        "mma.sync.aligned.m16n8k8.row.col.f32.tf32.tf32.f32 "
        "{%0,%1,%2,%3}, {%4,%5,%6,%7}, {%8,%9}, {%0,%1,%2,%3};"
        : "+f"(c[0]), "+f"(c[1]), "+f"(c[2]), "+f"(c[3])
        : "r"(a[0]), "r"(a[1]), "r"(a[2]), "r"(a[3]), "r"(b[0]), "r"(b[1]));
}

__device__ __forceinline__ void mma_bf16(float* c, const uint32_t* a, const uint32_t* b) {
    asm volatile(
        "mma.sync.aligned.m16n8k16.row.col.f32.bf16.bf16.f32 "
        "{%0,%1,%2,%3}, {%4,%5,%6,%7}, {%8,%9}, {%0,%1,%2,%3};"
        : "+f"(c[0]), "+f"(c[1]), "+f"(c[2]), "+f"(c[3])
        : "r"(a[0]), "r"(a[1]), "r"(a[2]), "r"(a[3]), "r"(b[0]), "r"(b[1]));
}

__device__ __forceinline__ void split_pack_bf16(float x, float y,
                                                uint32_t& hi, uint32_t& lo) {
    __nv_bfloat16 hx = __float2bfloat16(x);
    __nv_bfloat16 hy = __float2bfloat16(y);
    __nv_bfloat16 lx = __float2bfloat16(x - __bfloat162float(hx));
    __nv_bfloat16 ly = __float2bfloat16(y - __bfloat162float(hy));
    __nv_bfloat162 h; h.x = hx; h.y = hy;
    __nv_bfloat162 l; l.x = lx; l.y = ly;
    hi = *(uint32_t*)&h;
    lo = *(uint32_t*)&l;
}

__device__ __forceinline__ void cp16(uint32_t smem_dst, const void* gptr) {
    asm volatile("cp.async.cg.shared.global [%0], [%1], 16;\n"
                 :: "r"(smem_dst), "l"(gptr));
}

// ---------------------------------------------------------------------------
// Elementwise tf32 rounding pass (float4 grid-stride)
// ---------------------------------------------------------------------------
__global__ __launch_bounds__(256) void cvt_tf32_kernel(
    const float4* __restrict__ src, float4* __restrict__ dst, int n4)
{
    for (int i = blockIdx.x * 256 + threadIdx.x; i < n4; i += gridDim.x * 256) {
        float4 v = src[i];
        float4 o;
        o.x = __uint_as_float(f2tf32(v.x));
        o.y = __uint_as_float(f2tf32(v.y));
        o.z = __uint_as_float(f2tf32(v.z));
        o.w = __uint_as_float(f2tf32(v.w));
        dst[i] = o;
    }
}

// ---------------------------------------------------------------------------
// TF32 tensor-core GEMM, cp.async double-buffered, NO cvt (operands pre-tf32).
// BM=128, BN=64, BK=32, 128 threads (4 warps 2x2), warp tile 64x32 (4x4 frags).
// dynamic smem: 2 stages x (128*36 + 32*72) floats = 13824 f = 55296 B
// ---------------------------------------------------------------------------
#define GEMM_STAGE_FLOATS (128 * 36 + 32 * 72)
#define GEMM_SMEM_BYTES (2 * GEMM_STAGE_FLOATS * 4)

__global__ __launch_bounds__(128) void gemm_tf32_cp(
    const float* __restrict__ A, const float* __restrict__ B,
    const float* __restrict__ bias, float* __restrict__ C,
    int M, int N, int K)
{
    constexpr int ASTR = 36, BSTR = 72;

    extern __shared__ float sm[];

    const int tid = threadIdx.x;
    const int wid = tid >> 5;
    const int lane = tid & 31;
    const int lr = lane >> 2;
    const int lc = lane & 3;
    const int wm = wid & 1;     // 2 m-tiles of 64
    const int wn = wid >> 1;    // 2 n-tiles of 32

    const int bm = blockIdx.y * 128;
    const int bn = blockIdx.x * 64;

    const uint32_t smem_base = (uint32_t)__cvta_generic_to_shared(sm);

    // issue one K-tile into stage s
    auto issue = [&](int k0, int s) {
        const uint32_t as_base = smem_base + (uint32_t)(s * GEMM_STAGE_FLOATS) * 4;
        const uint32_t bs_base = as_base + 128 * ASTR * 4;
        #pragma unroll
        for (int i = 0; i < 8; i++) {
            const int idx = tid + 128 * i;
            const int r = idx >> 3, c4 = idx & 7;
            cp16(as_base + (r * ASTR + c4 * 4) * 4,
                 A + (size_t)(bm + r) * K + k0 + c4 * 4);
        }
        #pragma unroll
        for (int i = 0; i < 4; i++) {
            const int idx = tid + 128 * i;
            const int r = idx >> 4, c4 = idx & 15;
            cp16(bs_base + (r * BSTR + c4 * 4) * 4,
                 B + (size_t)(k0 + r) * N + bn + c4 * 4);
        }
        asm volatile("cp.async.commit_group;\n" ::);
    };

    float acc[4][4][4] = {};   // [mi][ni][frag]

    const int niter = K / 32;
    issue(0, 0);
    if (niter > 1) issue(32, 1);

    for (int it = 0; it < niter; it++) {
        if (it < niter - 1)
            asm volatile("cp.async.wait_group 1;\n" ::);
        else
            asm volatile("cp.async.wait_group 0;\n" ::);
        __syncthreads();

        const float* As = sm + (it & 1) * GEMM_STAGE_FLOATS;
        const float* Bs = As + 128 * ASTR;

        #pragma unroll
        for (int ks = 0; ks < 4; ks++) {
            const int k = ks * 8;
            uint32_t afr[4][4];
            #pragma unroll
            for (int mi = 0; mi < 4; mi++) {
                const int r = wm * 64 + mi * 16;
                afr[mi][0] = __float_as_uint(As[(r + lr) * ASTR + k + lc]);
                afr[mi][1] = __float_as_uint(As[(r + 8 + lr) * ASTR + k + lc]);
                afr[mi][2] = __float_as_uint(As[(r + lr) * ASTR + k + 4 + lc]);
                afr[mi][3] = __float_as_uint(As[(r + 8 + lr) * ASTR + k + 4 + lc]);
            }
            uint32_t bfr[4][2];
            #pragma unroll
            for (int ni = 0; ni < 4; ni++) {
                const int c = wn * 32 + ni * 8 + lr;
                bfr[ni][0] = __float_as_uint(Bs[(k + lc) * BSTR + c]);
                bfr[ni][1] = __float_as_uint(Bs[(k + 4 + lc) * BSTR + c]);
            }
            #pragma unroll
            for (int mi = 0; mi < 4; mi++)
                #pragma unroll
                for (int ni = 0; ni < 4; ni++)
                    mma_tf32(acc[mi][ni], afr[mi], bfr[ni]);
        }
        __syncthreads();   // all reads of this stage done before re-issue

        if (it + 2 < niter) issue((it + 2) * 32, it & 1);
    }

    // epilogue
    #pragma unroll
    for (int mi = 0; mi < 4; mi++) {
        #pragma unroll
        for (int ni = 0; ni < 4; ni++) {
            const int r0 = bm + wm * 64 + mi * 16 + lr;
            const int c0 = bn + wn * 32 + ni * 8 + lc * 2;
            float2 b01 = *(const float2*)(bias + c0);
            float2 v0 = make_float2(acc[mi][ni][0] + b01.x, acc[mi][ni][1] + b01.y);
            float2 v1 = make_float2(acc[mi][ni][2] + b01.x, acc[mi][ni][3] + b01.y);
            *(float2*)(C + (size_t)r0 * N + c0) = v0;
            *(float2*)(C + (size_t)(r0 + 8) * N + c0) = v1;
        }
    }
}

// ---------------------------------------------------------------------------
// comb[w][h][i][j] = mask[w][i][j] + bias_table[rel_index[i*49+j]][h]
// ---------------------------------------------------------------------------
__global__ __launch_bounds__(256) void comb_kernel(
    const float* __restrict__ mask, const float* __restrict__ bias_table,
    const int* __restrict__ rel_index, float* __restrict__ comb)
{
    const int total = NWIN * HEADS * NTOK * NTOK;
    int idx = blockIdx.x * 256 + threadIdx.x;
    if (idx < total) {
        const int ij = idx % (NTOK * NTOK);
        const int wh = idx / (NTOK * NTOK);
        const int h = wh & (HEADS - 1);
        const int w = wh >> 3;
        comb[idx] = mask[w * NTOK * NTOK + ij] + bias_table[rel_index[ij] * HEADS + h];
    }
}

// ---------------------------------------------------------------------------
// bf16 split-2, 3-term tensor-core window attention (round-6 known-good),
// now storing outputs tf32-rounded so proj GEMM needs no cvt.
// ---------------------------------------------------------------------------
#define ATTN_SMEM_BYTES (12992 * 4)

__global__ __launch_bounds__(128) void attn_bf16_kernel(
    const float* __restrict__ qkv,       // [B, N, 768]
    const float* __restrict__ comb,      // [64][8][49][49]
    float* __restrict__ out)             // [B, N, 256] (tf32-rounded)
{
    extern __shared__ __align__(16) uint32_t sw[];
    uint32_t* Qh  = sw;
    uint32_t* Ql  = sw + 1280;
    uint32_t* Ph  = sw;            // overlays Q after S phase
    uint32_t* Pl  = sw + 2304;
    uint32_t* Kh  = sw + 4608;
    uint32_t* Kl  = sw + 5728;
    uint32_t* Vth = sw + 6848;
    uint32_t* Vtl = sw + 8000;
    float*    Ss  = (float*)(sw + 9152);

    const int b = blockIdx.x;
    const int h = blockIdx.y;
    const int tid = threadIdx.x;
    const int wid = tid >> 5;
    const int lane = tid & 31;
    const int lr = lane >> 2;
    const int lc = lane & 3;

    const float scale = 0.17677669529663687f;
    const float* base = qkv + (size_t)b * NTOK * 3 * DIM + h * HD;

    // zero V-transpose pad halves j = 49..63 (both planes)
    {
        __nv_bfloat16* vhH = (__nv_bfloat16*)Vth;
        __nv_bfloat16* vlH = (__nv_bfloat16*)Vtl;
        for (int e = tid; e < HD * 15; e += 128) {
            const int d = e / 15;
            const int j = NTOK + (e % 15);
            vhH[d * 72 + j] = __float2bfloat16(0.f);
            vlH[d * 72 + j] = __float2bfloat16(0.f);
        }
    }

    {
        __nv_bfloat16* vhH = (__nv_bfloat16*)Vth;
        __nv_bfloat16* vlH = (__nv_bfloat16*)Vtl;
        for (int pe = tid; pe < NTOK * (HD / 2); pe += 128) {
            const int n = pe >> 4;
            const int dp = pe & 15;
            const int d = dp * 2;
            const float* row = base + (size_t)n * (3 * DIM) + d;
            float2 q2 = *(const float2*)(row);
            float2 k2 = *(const float2*)(row + DIM);
            float2 v2 = *(const float2*)(row + 2 * DIM);
            q2.x *= scale; q2.y *= scale;

            uint32_t hi, lo;
            split_pack_bf16(q2.x, q2.y, hi, lo);
            Qh[n * 20 + dp] = hi;
            Ql[n * 20 + dp] = lo;
            split_pack_bf16(k2.x, k2.y, hi, lo);
            Kh[n * 20 + dp] = hi;
            Kl[n * 20 + dp] = lo;

            __nv_bfloat16 vh0 = __float2bfloat16(v2.x);
            __nv_bfloat16 vh1 = __float2bfloat16(v2.y);
            __nv_bfloat16 vl0 = __float2bfloat16(v2.x - __bfloat162float(vh0));
            __nv_bfloat16 vl1 = __float2bfloat16(v2.y - __bfloat162float(vh1));
            vhH[d * 72 + n] = vh0;
            vhH[(d + 1) * 72 + n] = vh1;
            vlH[d * 72 + n] = vl0;
            vlH[(d + 1) * 72 + n] = vl1;
        }
    }
    __syncthreads();

    const int mr = wid * 16;

    // ---- S = (Q*scale) @ K^T ----
    {
        float sacc[7][4] = {};
        #pragma unroll
        for (int kt = 0; kt < 2; kt++) {
            const int kw = kt * 8;
            uint32_t ah[4], al[4];
            ah[0] = Qh[(mr + lr) * 20 + kw + lc];
            ah[1] = Qh[(mr + 8 + lr) * 20 + kw + lc];
            ah[2] = Qh[(mr + lr) * 20 + kw + 4 + lc];
            ah[3] = Qh[(mr + 8 + lr) * 20 + kw + 4 + lc];
            al[0] = Ql[(mr + lr) * 20 + kw + lc];
            al[1] = Ql[(mr + 8 + lr) * 20 + kw + lc];
            al[2] = Ql[(mr + lr) * 20 + kw + 4 + lc];
            al[3] = Ql[(mr + 8 + lr) * 20 + kw + 4 + lc];

            #pragma unroll
            for (int nt = 0; nt < 7; nt++) {
                const int n0 = nt * 8;
                uint32_t bh[2], bl[2];
                bh[0] = Kh[(n0 + lr) * 20 + kw + lc];
                bh[1] = Kh[(n0 + lr) * 20 + kw + 4 + lc];
                bl[0] = Kl[(n0 + lr) * 20 + kw + lc];
                bl[1] = Kl[(n0 + lr) * 20 + kw + 4 + lc];
                mma_bf16(sacc[nt], ah, bh);
                mma_bf16(sacc[nt], al, bh);
                mma_bf16(sacc[nt], ah, bl);
            }
        }
        #pragma unroll
        for (int nt = 0; nt < 7; nt++) {
            const int c0 = nt * 8 + lc * 2;
            Ss[(mr + lr) * 60 + c0] = sacc[nt][0];
            Ss[(mr + lr) * 60 + c0 + 1] = sacc[nt][1];
            Ss[(mr + 8 + lr) * 60 + c0] = sacc[nt][2];
            Ss[(mr + 8 + lr) * 60 + c0 + 1] = sacc[nt][3];
        }
    }
    __syncthreads();

    // ---- softmax + split P ----
    {
        const float* cb = comb + ((size_t)((b & (NWIN - 1)) * HEADS + h)) * (NTOK * NTOK);
        __nv_bfloat16* phH = (__nv_bfloat16*)Ph;
        __nv_bfloat16* plH = (__nv_bfloat16*)Pl;
        for (int i = wid; i < NTOK; i += 4) {
            const int j1 = lane + 32;
            float v0 = Ss[i * 60 + lane] + cb[i * NTOK + lane];
            float v1 = (j1 < NTOK) ? (Ss[i * 60 + j1] + cb[i * NTOK + j1]) : -CUDART_INF_F;
            float m = fmaxf(v0, v1);
            #pragma unroll
            for (int o = 16; o > 0; o >>= 1) m = fmaxf(m, __shfl_xor_sync(0xffffffffu, m, o));
            float e0 = __expf(v0 - m);
            float e1 = (j1 < NTOK) ? __expf(v1 - m) : 0.f;
            float s = e0 + e1;
            #pragma unroll
            for (int o = 16; o > 0; o >>= 1) s += __shfl_xor_sync(0xffffffffu, s, o);
            const float inv = 1.f / s;
            float p0 = e0 * inv;
            float p1 = e1 * inv;

            __nv_bfloat16 h0 = __float2bfloat16(p0);
            __nv_bfloat16 l0 = __float2bfloat16(p0 - __bfloat162float(h0));
            __nv_bfloat16 h1 = __float2bfloat16(p1);
            __nv_bfloat16 l1 = __float2bfloat16(p1 - __bfloat162float(h1));
            phH[i * 72 + lane] = h0;
            phH[i * 72 + j1]   = h1;
            plH[i * 72 + lane] = l0;
            plH[i * 72 + j1]   = l1;
        }
    }
    __syncthreads();

    // ---- O = P @ V ----
    {
        float oacc[4][4] = {};
        #pragma unroll
        for (int kt = 0; kt < 4; kt++) {
            const int kw = kt * 8;
            uint32_t ah[4], al[4];
            ah[0] = Ph[(mr + lr) * 36 + kw + lc];
            ah[1] = Ph[(mr + 8 + lr) * 36 + kw + lc];
            ah[2] = Ph[(mr + lr) * 36 + kw + 4 + lc];
            ah[3] = Ph[(mr + 8 + lr) * 36 + kw + 4 + lc];
            al[0] = Pl[(mr + lr) * 36 + kw + lc];
            al[1] = Pl[(mr + 8 + lr) * 36 + kw + lc];
            al[2] = Pl[(mr + lr) * 36 + kw + 4 + lc];
            al[3] = Pl[(mr + 8 + lr) * 36 + kw + 4 + lc];

            #pragma unroll
            for (int nt = 0; nt < 4; nt++) {
                const int n0 = nt * 8;
                uint32_t bh[2], bl[2];
                bh[0] = Vth[(n0 + lr) * 36 + kw + lc];
                bh[1] = Vth[(n0 + lr) * 36 + kw + 4 + lc];
                bl[0] = Vtl[(n0 + lr) * 36 + kw + lc];
                bl[1] = Vtl[(n0 + lr) * 36 + kw + 4 + lc];
                mma_bf16(oacc[nt], ah, bh);
                mma_bf16(oacc[nt], al, bh);
                mma_bf16(oacc[nt], ah, bl);
            }
        }

        const int r0 = mr + lr;
        const int r1 = mr + 8 + lr;
        #pragma unroll
        for (int nt = 0; nt < 4; nt++) {
            const int c0 = h * HD + nt * 8 + lc * 2;
            if (r0 < NTOK) {
                float2 v = make_float2(__uint_as_float(f2tf32(oacc[nt][0])),
                                       __uint_as_float(f2tf32(oacc[nt][1])));
                *(float2*)(out + ((size_t)b * NTOK + r0) * DIM + c0) = v;
            }
            if (r1 < NTOK) {
                float2 v = make_float2(__uint_as_float(f2tf32(oacc[nt][2])),
                                       __uint_as_float(f2tf32(oacc[nt][3])));
                *(float2*)(out + ((size_t)b * NTOK + r1) * DIM + c0) = v;
            }
        }
    }
}

// ---------------------------------------------------------------------------
extern "C" void kernel_launch(void* const* d_in, const int* in_sizes, int n_in,
                              void* d_out, int out_size)
{
    const float* x          = (const float*)d_in[0];
    const float* mask       = (const float*)d_in[1];
    const float* qkv_w      = (const float*)d_in[2];
    const float* qkv_b      = (const float*)d_in[3];
    const float* proj_w     = (const float*)d_in[4];
    const float* proj_b     = (const float*)d_in[5];
    const float* bias_table = (const float*)d_in[6];
    const int*   rel_index  = (const int*)d_in[7];
    float* out = (float*)d_out;

    float *xt_buf, *qkv_buf, *ao_buf, *wq_buf, *wp_buf, *comb_buf;
    cudaGetSymbolAddress((void**)&xt_buf, g_xt);
    cudaGetSymbolAddress((void**)&qkv_buf, g_qkv);
    cudaGetSymbolAddress((void**)&ao_buf, g_ao);
    cudaGetSymbolAddress((void**)&wq_buf, g_wq);
    cudaGetSymbolAddress((void**)&wp_buf, g_wp);
    cudaGetSymbolAddress((void**)&comb_buf, g_comb);

    static bool attr_set = false;
    if (!attr_set) {
        cudaFuncSetAttribute(attn_bf16_kernel,
                             cudaFuncAttributeMaxDynamicSharedMemorySize,
                             ATTN_SMEM_BYTES);
        cudaFuncSetAttribute(gemm_tf32_cp,
                             cudaFuncAttributeMaxDynamicSharedMemorySize,
                             GEMM_SMEM_BYTES);
        attr_set = true;
    }

    const int M = BATCH * NTOK;   // 100352 = 128 * 784

    // 0a) tf32-round x and weights
    {
        const int n4x = M * DIM / 4;
        cvt_tf32_kernel<<<2048, 256>>>((const float4*)x, (float4*)xt_buf, n4x);
        cvt_tf32_kernel<<<192, 256>>>((const float4*)qkv_w, (float4*)wq_buf,
                                      DIM * 3 * DIM / 4);
        cvt_tf32_kernel<<<64, 256>>>((const float4*)proj_w, (float4*)wp_buf,
                                     DIM * DIM / 4);
    }
    // 0b) combined bias+mask table
    {
        const int total = NWIN * HEADS * NTOK * NTOK;
        comb_kernel<<<(total + 255) / 256, 256>>>(mask, bias_table, rel_index, comb_buf);
    }
    // 1) QKV GEMM: [M,256] @ [256,768] + b
    {
        dim3 grid(3 * DIM / 64, M / 128);
        gemm_tf32_cp<<<grid, 128, GEMM_SMEM_BYTES>>>(xt_buf, wq_buf, qkv_b, qkv_buf,
                                                     M, 3 * DIM, DIM);
    }
    // 2) bf16 tensor-core window attention (stores tf32-rounded)
    {
        dim3 grid(BATCH, HEADS);
        attn_bf16_kernel<<<grid, 128, ATTN_SMEM_BYTES>>>(qkv_buf, comb_buf, ao_buf);
    }
    // 3) Proj GEMM: [M,256] @ [256,256] + b
    {
        dim3 grid(DIM / 64, M / 128);
        gemm_tf32_cp<<<grid, 128, GEMM_SMEM_BYTES>>>(ao_buf, wp_buf, proj_b, out,
                                                     M, DIM, DIM);
    }
}

// round 8
// speedup vs baseline: 1.9141x; 1.3203x over previous
#include <cuda_runtime.h>
#include <cuda_bf16.h>
#include <cstdint>
#include <math_constants.h>

#define HEADS 8
#define HD 32
#define NTOK 49
#define DIM 256
#define BATCH 2048
#define NWIN 64

// scratch (allocation-free rule: device globals)
__device__ float g_xt[(size_t)BATCH * NTOK * DIM];           // tf32(x)
__device__ float g_qkv[(size_t)BATCH * NTOK * 3 * DIM];      // [B, N, 768]
__device__ float g_ao[(size_t)BATCH * NTOK * DIM];           // attention out (tf32-rounded)
__device__ float g_wq[DIM * 3 * DIM];                        // tf32(qkv_w)
__device__ float g_wp[DIM * DIM];                            // tf32(proj_w)
__device__ float g_comb[(size_t)NWIN * HEADS * NTOK * NTOK]; // [w][h][i][j]

__device__ __forceinline__ uint32_t f2tf32(float x) {
    uint32_t u;
    asm("cvt.rna.tf32.f32 %0, %1;" : "=r"(u) : "f"(x));
    return u;
}

__device__ __forceinline__ void mma_tf32(float* c, const uint32_t* a, const uint32_t* b) {
    asm volatile(
        "mma.sync.aligned.m16n8k8.row.col.f32.tf32.tf32.f32 "
        "{%0,%1,%2,%3}, {%4,%5,%6,%7}, {%8,%9}, {%0,%1,%2,%3};"
        : "+f"(c[0]), "+f"(c[1]), "+f"(c[2]), "+f"(c[3])
        : "r"(a[0]), "r"(a[1]), "r"(a[2]), "r"(a[3]), "r"(b[0]), "r"(b[1]));
}

__device__ __forceinline__ void mma_bf16(float* c, const uint32_t* a, const uint32_t* b) {
    asm volatile(
        "mma.sync.aligned.m16n8k16.row.col.f32.bf16.bf16.f32 "
        "{%0,%1,%2,%3}, {%4,%5,%6,%7}, {%8,%9}, {%0,%1,%2,%3};"
        : "+f"(c[0]), "+f"(c[1]), "+f"(c[2]), "+f"(c[3])
        : "r"(a[0]), "r"(a[1]), "r"(a[2]), "r"(a[3]), "r"(b[0]), "r"(b[1]));
}

__device__ __forceinline__ void split_pack_bf16(float x, float y,
                                                uint32_t& hi, uint32_t& lo) {
    __nv_bfloat16 hx = __float2bfloat16(x);
    __nv_bfloat16 hy = __float2bfloat16(y);
    __nv_bfloat16 lx = __float2bfloat16(x - __bfloat162float(hx));
    __nv_bfloat16 ly = __float2bfloat16(y - __bfloat162float(hy));
    __nv_bfloat162 h; h.x = hx; h.y = hy;
    __nv_bfloat162 l; l.x = lx; l.y = ly;
    hi = *(uint32_t*)&h;
    lo = *(uint32_t*)&l;
}

__device__ __forceinline__ void cp16(uint32_t smem_dst, const void* gptr) {
    asm volatile("cp.async.cg.shared.global [%0], [%1], 16;\n"
                 :: "r"(smem_dst), "l"(gptr));
}

// ---------------------------------------------------------------------------
// Elementwise tf32 rounding pass (float4 grid-stride)
// ---------------------------------------------------------------------------
__global__ __launch_bounds__(256) void cvt_tf32_kernel(
    const float4* __restrict__ src, float4* __restrict__ dst, int n4)
{
    for (int i = blockIdx.x * 256 + threadIdx.x; i < n4; i += gridDim.x * 256) {
        float4 v = src[i];
        float4 o;
        o.x = __uint_as_float(f2tf32(v.x));
        o.y = __uint_as_float(f2tf32(v.y));
        o.z = __uint_as_float(f2tf32(v.z));
        o.w = __uint_as_float(f2tf32(v.w));
        dst[i] = o;
    }
}

// ---------------------------------------------------------------------------
// TF32 tensor-core GEMM, cp.async double-buffered (round-7 known good)
// ---------------------------------------------------------------------------
#define GEMM_STAGE_FLOATS (128 * 36 + 32 * 72)
#define GEMM_SMEM_BYTES (2 * GEMM_STAGE_FLOATS * 4)

__global__ __launch_bounds__(128) void gemm_tf32_cp(
    const float* __restrict__ A, const float* __restrict__ B,
    const float* __restrict__ bias, float* __restrict__ C,
    int M, int N, int K)
{
    constexpr int ASTR = 36, BSTR = 72;

    extern __shared__ float sm[];

    const int tid = threadIdx.x;
    const int wid = tid >> 5;
    const int lane = tid & 31;
    const int lr = lane >> 2;
    const int lc = lane & 3;
    const int wm = wid & 1;
    const int wn = wid >> 1;

    const int bm = blockIdx.y * 128;
    const int bn = blockIdx.x * 64;

    const uint32_t smem_base = (uint32_t)__cvta_generic_to_shared(sm);

    auto issue = [&](int k0, int s) {
        const uint32_t as_base = smem_base + (uint32_t)(s * GEMM_STAGE_FLOATS) * 4;
        const uint32_t bs_base = as_base + 128 * ASTR * 4;
        #pragma unroll
        for (int i = 0; i < 8; i++) {
            const int idx = tid + 128 * i;
            const int r = idx >> 3, c4 = idx & 7;
            cp16(as_base + (r * ASTR + c4 * 4) * 4,
                 A + (size_t)(bm + r) * K + k0 + c4 * 4);
        }
        #pragma unroll
        for (int i = 0; i < 4; i++) {
            const int idx = tid + 128 * i;
            const int r = idx >> 4, c4 = idx & 15;
            cp16(bs_base + (r * BSTR + c4 * 4) * 4,
                 B + (size_t)(k0 + r) * N + bn + c4 * 4);
        }
        asm volatile("cp.async.commit_group;\n" ::);
    };

    float acc[4][4][4] = {};

    const int niter = K / 32;
    issue(0, 0);
    if (niter > 1) issue(32, 1);

    for (int it = 0; it < niter; it++) {
        if (it < niter - 1)
            asm volatile("cp.async.wait_group 1;\n" ::);
        else
            asm volatile("cp.async.wait_group 0;\n" ::);
        __syncthreads();

        const float* As = sm + (it & 1) * GEMM_STAGE_FLOATS;
        const float* Bs = As + 128 * ASTR;

        #pragma unroll
        for (int ks = 0; ks < 4; ks++) {
            const int k = ks * 8;
            uint32_t afr[4][4];
            #pragma unroll
            for (int mi = 0; mi < 4; mi++) {
                const int r = wm * 64 + mi * 16;
                afr[mi][0] = __float_as_uint(As[(r + lr) * ASTR + k + lc]);
                afr[mi][1] = __float_as_uint(As[(r + 8 + lr) * ASTR + k + lc]);
                afr[mi][2] = __float_as_uint(As[(r + lr) * ASTR + k + 4 + lc]);
                afr[mi][3] = __float_as_uint(As[(r + 8 + lr) * ASTR + k + 4 + lc]);
            }
            uint32_t bfr[4][2];
            #pragma unroll
            for (int ni = 0; ni < 4; ni++) {
                const int c = wn * 32 + ni * 8 + lr;
                bfr[ni][0] = __float_as_uint(Bs[(k + lc) * BSTR + c]);
                bfr[ni][1] = __float_as_uint(Bs[(k + 4 + lc) * BSTR + c]);
            }
            #pragma unroll
            for (int mi = 0; mi < 4; mi++)
                #pragma unroll
                for (int ni = 0; ni < 4; ni++)
                    mma_tf32(acc[mi][ni], afr[mi], bfr[ni]);
        }
        __syncthreads();

        if (it + 2 < niter) issue((it + 2) * 32, it & 1);
    }

    #pragma unroll
    for (int mi = 0; mi < 4; mi++) {
        #pragma unroll
        for (int ni = 0; ni < 4; ni++) {
            const int r0 = bm + wm * 64 + mi * 16 + lr;
            const int c0 = bn + wn * 32 + ni * 8 + lc * 2;
            float2 b01 = *(const float2*)(bias + c0);
            float2 v0 = make_float2(acc[mi][ni][0] + b01.x, acc[mi][ni][1] + b01.y);
            float2 v1 = make_float2(acc[mi][ni][2] + b01.x, acc[mi][ni][3] + b01.y);
            *(float2*)(C + (size_t)r0 * N + c0) = v0;
            *(float2*)(C + (size_t)(r0 + 8) * N + c0) = v1;
        }
    }
}

// ---------------------------------------------------------------------------
// comb[w][h][i][j] = mask[w][i][j] + bias_table[rel_index[i*49+j]][h]
// ---------------------------------------------------------------------------
__global__ __launch_bounds__(256) void comb_kernel(
    const float* __restrict__ mask, const float* __restrict__ bias_table,
    const int* __restrict__ rel_index, float* __restrict__ comb)
{
    const int total = NWIN * HEADS * NTOK * NTOK;
    int idx = blockIdx.x * 256 + threadIdx.x;
    if (idx < total) {
        const int ij = idx % (NTOK * NTOK);
        const int wh = idx / (NTOK * NTOK);
        const int h = wh & (HEADS - 1);
        const int w = wh >> 3;
        comb[idx] = mask[w * NTOK * NTOK + ij] + bias_table[rel_index[ij] * HEADS + h];
    }
}

// ---------------------------------------------------------------------------
// Register-resident-softmax bf16 attention. One block per (b, h), 4 warps.
// S frags stay in registers; softmax via quad shuffles; P packed directly
// into PV A-frags. Single __syncthreads. Static smem 28416 B.
// ---------------------------------------------------------------------------
__global__ __launch_bounds__(128) void attn_reg_kernel(
    const float* __restrict__ qkv,       // [B, N, 768]
    const float* __restrict__ comb,      // [64][8][49][49]
    float* __restrict__ out)             // [B, N, 256] (tf32-rounded)
{
    __shared__ __align__(16) uint32_t sw[7104];
    uint32_t* Qh  = sw;            // 64 x 20
    uint32_t* Ql  = sw + 1280;
    uint32_t* Kh  = sw + 2560;     // 56 x 20
    uint32_t* Kl  = sw + 3680;
    uint32_t* Vth = sw + 4800;     // 32 x 36 (V transposed [d][j])
    uint32_t* Vtl = sw + 5952;

    const int b = blockIdx.x;
    const int h = blockIdx.y;
    const int tid = threadIdx.x;
    const int wid = tid >> 5;
    const int lane = tid & 31;
    const int lr = lane >> 2;
    const int lc = lane & 3;

    const float scale = 0.17677669529663687f;
    const float* base = qkv + (size_t)b * NTOK * 3 * DIM + h * HD;

    // zero V-transpose pad halves j = 49..63 (both planes)
    {
        __nv_bfloat16* vhH = (__nv_bfloat16*)Vth;
        __nv_bfloat16* vlH = (__nv_bfloat16*)Vtl;
        for (int e = tid; e < HD * 15; e += 128) {
            const int d = e / 15;
            const int j = NTOK + (e % 15);
            vhH[d * 72 + j] = __float2bfloat16(0.f);
            vlH[d * 72 + j] = __float2bfloat16(0.f);
        }
    }

    // load q/k/v; split into bf16 hi/lo planes
    {
        __nv_bfloat16* vhH = (__nv_bfloat16*)Vth;
        __nv_bfloat16* vlH = (__nv_bfloat16*)Vtl;
        for (int pe = tid; pe < NTOK * (HD / 2); pe += 128) {
            const int n = pe >> 4;
            const int dp = pe & 15;
            const int d = dp * 2;
            const float* row = base + (size_t)n * (3 * DIM) + d;
            float2 q2 = *(const float2*)(row);
            float2 k2 = *(const float2*)(row + DIM);
            float2 v2 = *(const float2*)(row + 2 * DIM);
            q2.x *= scale; q2.y *= scale;

            uint32_t hi, lo;
            split_pack_bf16(q2.x, q2.y, hi, lo);
            Qh[n * 20 + dp] = hi;
            Ql[n * 20 + dp] = lo;
            split_pack_bf16(k2.x, k2.y, hi, lo);
            Kh[n * 20 + dp] = hi;
            Kl[n * 20 + dp] = lo;

            __nv_bfloat16 vh0 = __float2bfloat16(v2.x);
            __nv_bfloat16 vh1 = __float2bfloat16(v2.y);
            __nv_bfloat16 vl0 = __float2bfloat16(v2.x - __bfloat162float(vh0));
            __nv_bfloat16 vl1 = __float2bfloat16(v2.y - __bfloat162float(vh1));
            vhH[d * 72 + n] = vh0;
            vhH[(d + 1) * 72 + n] = vh1;
            vlH[d * 72 + n] = vl0;
            vlH[(d + 1) * 72 + n] = vl1;
        }
    }
    __syncthreads();

    const int mr = wid * 16;

    // ---- S = (Q*scale) @ K^T  (frags stay in registers) ----
    float sacc[7][4] = {};
    #pragma unroll
    for (int kt = 0; kt < 2; kt++) {
        const int kw = kt * 8;
        uint32_t ah[4], al[4];
        ah[0] = Qh[(mr + lr) * 20 + kw + lc];
        ah[1] = Qh[(mr + 8 + lr) * 20 + kw + lc];
        ah[2] = Qh[(mr + lr) * 20 + kw + 4 + lc];
        ah[3] = Qh[(mr + 8 + lr) * 20 + kw + 4 + lc];
        al[0] = Ql[(mr + lr) * 20 + kw + lc];
        al[1] = Ql[(mr + 8 + lr) * 20 + kw + lc];
        al[2] = Ql[(mr + lr) * 20 + kw + 4 + lc];
        al[3] = Ql[(mr + 8 + lr) * 20 + kw + 4 + lc];

        #pragma unroll
        for (int nt = 0; nt < 7; nt++) {
            const int n0 = nt * 8;
            uint32_t bh[2], bl[2];
            bh[0] = Kh[(n0 + lr) * 20 + kw + lc];
            bh[1] = Kh[(n0 + lr) * 20 + kw + 4 + lc];
            bl[0] = Kl[(n0 + lr) * 20 + kw + lc];
            bl[1] = Kl[(n0 + lr) * 20 + kw + 4 + lc];
            mma_bf16(sacc[nt], ah, bh);
            mma_bf16(sacc[nt], al, bh);
            mma_bf16(sacc[nt], ah, bl);
        }
    }

    // ---- register softmax: add comb, quad-shuffle max/sum, normalize ----
    {
        const float* cb = comb + ((size_t)((b & (NWIN - 1)) * HEADS + h)) * (NTOK * NTOK);
        const int rA = mr + lr;
        const int rB = mr + 8 + lr;
        const bool okA = rA < NTOK;
        const bool okB = rB < NTOK;
        float mA = -CUDART_INF_F, mB = -CUDART_INF_F;

        #pragma unroll
        for (int nt = 0; nt < 7; nt++) {
            const int c0 = nt * 8 + 2 * lc;
            const bool ok0 = c0 < NTOK;
            const bool ok1 = (c0 + 1) < NTOK;
            float v0A = (okA && ok0) ? sacc[nt][0] + __ldg(cb + rA * NTOK + c0)     : -CUDART_INF_F;
            float v1A = (okA && ok1) ? sacc[nt][1] + __ldg(cb + rA * NTOK + c0 + 1) : -CUDART_INF_F;
            float v0B = (okB && ok0) ? sacc[nt][2] + __ldg(cb + rB * NTOK + c0)     : -CUDART_INF_F;
            float v1B = (okB && ok1) ? sacc[nt][3] + __ldg(cb + rB * NTOK + c0 + 1) : -CUDART_INF_F;
            sacc[nt][0] = v0A; sacc[nt][1] = v1A;
            sacc[nt][2] = v0B; sacc[nt][3] = v1B;
            mA = fmaxf(mA, fmaxf(v0A, v1A));
            mB = fmaxf(mB, fmaxf(v0B, v1B));
        }
        mA = fmaxf(mA, __shfl_xor_sync(0xffffffffu, mA, 1));
        mA = fmaxf(mA, __shfl_xor_sync(0xffffffffu, mA, 2));
        mB = fmaxf(mB, __shfl_xor_sync(0xffffffffu, mB, 1));
        mB = fmaxf(mB, __shfl_xor_sync(0xffffffffu, mB, 2));

        float sA = 0.f, sB = 0.f;
        #pragma unroll
        for (int nt = 0; nt < 7; nt++) {
            float e0A = __expf(sacc[nt][0] - mA);
            float e1A = __expf(sacc[nt][1] - mA);
            float e0B = __expf(sacc[nt][2] - mB);
            float e1B = __expf(sacc[nt][3] - mB);
            sacc[nt][0] = e0A; sacc[nt][1] = e1A;
            sacc[nt][2] = e0B; sacc[nt][3] = e1B;
            sA += e0A + e1A;
            sB += e0B + e1B;
        }
        sA += __shfl_xor_sync(0xffffffffu, sA, 1);
        sA += __shfl_xor_sync(0xffffffffu, sA, 2);
        sB += __shfl_xor_sync(0xffffffffu, sB, 1);
        sB += __shfl_xor_sync(0xffffffffu, sB, 2);
        const float invA = 1.f / sA;
        const float invB = 1.f / sB;
        #pragma unroll
        for (int nt = 0; nt < 7; nt++) {
            sacc[nt][0] *= invA; sacc[nt][1] *= invA;
            sacc[nt][2] *= invB; sacc[nt][3] *= invB;
        }
    }

    // ---- O = P @ V : A-frags built directly from sacc registers ----
    {
        float oacc[4][4] = {};
        #pragma unroll
        for (int kt = 0; kt < 4; kt++) {
            const int kw = kt * 8;
            const int t0 = 2 * kt;
            const int t1 = 2 * kt + 1;
            uint32_t ah[4], al[4];
            split_pack_bf16(sacc[t0][0], sacc[t0][1], ah[0], al[0]);
            split_pack_bf16(sacc[t0][2], sacc[t0][3], ah[1], al[1]);
            if (t1 < 7) {
                split_pack_bf16(sacc[t1][0], sacc[t1][1], ah[2], al[2]);
                split_pack_bf16(sacc[t1][2], sacc[t1][3], ah[3], al[3]);
            } else {
                ah[2] = ah[3] = al[2] = al[3] = 0u;
            }

            #pragma unroll
            for (int nt = 0; nt < 4; nt++) {
                const int n0 = nt * 8;
                uint32_t bh[2], bl[2];
                bh[0] = Vth[(n0 + lr) * 36 + kw + lc];
                bh[1] = Vth[(n0 + lr) * 36 + kw + 4 + lc];
                bl[0] = Vtl[(n0 + lr) * 36 + kw + lc];
                bl[1] = Vtl[(n0 + lr) * 36 + kw + 4 + lc];
                mma_bf16(oacc[nt], ah, bh);
                mma_bf16(oacc[nt], al, bh);
                mma_bf16(oacc[nt], ah, bl);
            }
        }

        const int r0 = mr + lr;
        const int r1 = mr + 8 + lr;
        #pragma unroll
        for (int nt = 0; nt < 4; nt++) {
            const int c0 = h * HD + nt * 8 + lc * 2;
            if (r0 < NTOK) {
                float2 v = make_float2(__uint_as_float(f2tf32(oacc[nt][0])),
                                       __uint_as_float(f2tf32(oacc[nt][1])));
                *(float2*)(out + ((size_t)b * NTOK + r0) * DIM + c0) = v;
            }
            if (r1 < NTOK) {
                float2 v = make_float2(__uint_as_float(f2tf32(oacc[nt][2])),
                                       __uint_as_float(f2tf32(oacc[nt][3])));
                *(float2*)(out + ((size_t)b * NTOK + r1) * DIM + c0) = v;
            }
        }
    }
}

// ---------------------------------------------------------------------------
extern "C" void kernel_launch(void* const* d_in, const int* in_sizes, int n_in,
                              void* d_out, int out_size)
{
    const float* x          = (const float*)d_in[0];
    const float* mask       = (const float*)d_in[1];
    const float* qkv_w      = (const float*)d_in[2];
    const float* qkv_b      = (const float*)d_in[3];
    const float* proj_w     = (const float*)d_in[4];
    const float* proj_b     = (const float*)d_in[5];
    const float* bias_table = (const float*)d_in[6];
    const int*   rel_index  = (const int*)d_in[7];
    float* out = (float*)d_out;

    float *xt_buf, *qkv_buf, *ao_buf, *wq_buf, *wp_buf, *comb_buf;
    cudaGetSymbolAddress((void**)&xt_buf, g_xt);
    cudaGetSymbolAddress((void**)&qkv_buf, g_qkv);
    cudaGetSymbolAddress((void**)&ao_buf, g_ao);
    cudaGetSymbolAddress((void**)&wq_buf, g_wq);
    cudaGetSymbolAddress((void**)&wp_buf, g_wp);
    cudaGetSymbolAddress((void**)&comb_buf, g_comb);

    static bool attr_set = false;
    if (!attr_set) {
        cudaFuncSetAttribute(gemm_tf32_cp,
                             cudaFuncAttributeMaxDynamicSharedMemorySize,
                             GEMM_SMEM_BYTES);
        attr_set = true;
    }

    const int M = BATCH * NTOK;   // 100352 = 128 * 784

    // 0a) tf32-round x and weights
    {
        const int n4x = M * DIM / 4;
        cvt_tf32_kernel<<<2048, 256>>>((const float4*)x, (float4*)xt_buf, n4x);
        cvt_tf32_kernel<<<192, 256>>>((const float4*)qkv_w, (float4*)wq_buf,
                                      DIM * 3 * DIM / 4);
        cvt_tf32_kernel<<<64, 256>>>((const float4*)proj_w, (float4*)wp_buf,
                                     DIM * DIM / 4);
    }
    // 0b) combined bias+mask table
    {
        const int total = NWIN * HEADS * NTOK * NTOK;
        comb_kernel<<<(total + 255) / 256, 256>>>(mask, bias_table, rel_index, comb_buf);
    }
    // 1) QKV GEMM
    {
        dim3 grid(3 * DIM / 64, M / 128);
        gemm_tf32_cp<<<grid, 128, GEMM_SMEM_BYTES>>>(xt_buf, wq_buf, qkv_b, qkv_buf,
                                                     M, 3 * DIM, DIM);
    }
    // 2) register-softmax attention
    {
        dim3 grid(BATCH, HEADS);
        attn_reg_kernel<<<grid, 128>>>(qkv_buf, comb_buf, ao_buf);
    }
    // 3) Proj GEMM
    {
        dim3 grid(DIM / 64, M / 128);
        gemm_tf32_cp<<<grid, 128, GEMM_SMEM_BYTES>>>(ao_buf, wp_buf, proj_b, out,
                                                     M, DIM, DIM);
    }
}

// round 10
// speedup vs baseline: 2.0296x; 1.0604x over previous
#include <cuda_runtime.h>
#include <cuda_bf16.h>
#include <cstdint>
#include <math_constants.h>

#define HEADS 8
#define HD 32
#define NTOK 49
#define DIM 256
#define BATCH 2048
#define NWIN 64

// scratch (allocation-free rule: device globals)
__device__ float g_xt[(size_t)BATCH * NTOK * DIM];           // tf32(x)
__device__ float g_qkv[(size_t)BATCH * NTOK * 3 * DIM];      // [B, N, 768]
__device__ float g_ao[(size_t)BATCH * NTOK * DIM];           // attention out (tf32-rounded)
__device__ float g_wq[DIM * 3 * DIM];                        // tf32(qkv_w)
__device__ float g_wp[DIM * DIM];                            // tf32(proj_w)
__device__ float g_comb[(size_t)NWIN * HEADS * NTOK * NTOK]; // [w][h][i][j]

__device__ __forceinline__ uint32_t f2tf32(float x) {
    uint32_t u;
    asm("cvt.rna.tf32.f32 %0, %1;" : "=r"(u) : "f"(x));
    return u;
}

__device__ __forceinline__ void mma_tf32(float* c, const uint32_t* a, const uint32_t* b) {
    asm volatile(
        "mma.sync.aligned.m16n8k8.row.col.f32.tf32.tf32.f32 "
        "{%0,%1,%2,%3}, {%4,%5,%6,%7}, {%8,%9}, {%0,%1,%2,%3};"
        : "+f"(c[0]), "+f"(c[1]), "+f"(c[2]), "+f"(c[3])
        : "r"(a[0]), "r"(a[1]), "r"(a[2]), "r"(a[3]), "r"(b[0]), "r"(b[1]));
}

__device__ __forceinline__ void mma_bf16(float* c, const uint32_t* a, const uint32_t* b) {
    asm volatile(
        "mma.sync.aligned.m16n8k16.row.col.f32.bf16.bf16.f32 "
        "{%0,%1,%2,%3}, {%4,%5,%6,%7}, {%8,%9}, {%0,%1,%2,%3};"
        : "+f"(c[0]), "+f"(c[1]), "+f"(c[2]), "+f"(c[3])
        : "r"(a[0]), "r"(a[1]), "r"(a[2]), "r"(a[3]), "r"(b[0]), "r"(b[1]));
}

__device__ __forceinline__ void split_pack_bf16(float x, float y,
                                                uint32_t& hi, uint32_t& lo) {
    __nv_bfloat16 hx = __float2bfloat16(x);
    __nv_bfloat16 hy = __float2bfloat16(y);
    __nv_bfloat16 lx = __float2bfloat16(x - __bfloat162float(hx));
    __nv_bfloat16 ly = __float2bfloat16(y - __bfloat162float(hy));
    __nv_bfloat162 h; h.x = hx; h.y = hy;
    __nv_bfloat162 l; l.x = lx; l.y = ly;
    hi = *(uint32_t*)&h;
    lo = *(uint32_t*)&l;
}

__device__ __forceinline__ void cp16(uint32_t smem_dst, const void* gptr) {
    asm volatile("cp.async.cg.shared.global [%0], [%1], 16;\n"
                 :: "r"(smem_dst), "l"(gptr));
}

// ---------------------------------------------------------------------------
// Elementwise tf32 rounding pass (float4 grid-stride)
// ---------------------------------------------------------------------------
__global__ __launch_bounds__(256) void cvt_tf32_kernel(
    const float4* __restrict__ src, float4* __restrict__ dst, int n4)
{
    for (int i = blockIdx.x * 256 + threadIdx.x; i < n4; i += gridDim.x * 256) {
        float4 v = src[i];
        float4 o;
        o.x = __uint_as_float(f2tf32(v.x));
        o.y = __uint_as_float(f2tf32(v.y));
        o.z = __uint_as_float(f2tf32(v.z));
        o.w = __uint_as_float(f2tf32(v.w));
        dst[i] = o;
    }
}

// ---------------------------------------------------------------------------
// TF32 mma.sync GEMM, cp.async double-buffered, 64x64 warp tiles.
// BM=128, BN=128, BK=32, 128 threads (4 warps 2x2).
// smem: 2 stages x (128*36 + 32*136) floats = 71680 bytes -> 2 CTAs/SM
// ---------------------------------------------------------------------------
#define GEMM_STAGE_FLOATS (128 * 36 + 32 * 136)
#define GEMM_SMEM_BYTES (2 * GEMM_STAGE_FLOATS * 4)

__global__ __launch_bounds__(128) void gemm_tf32_w64(
    const float* __restrict__ A, const float* __restrict__ B,
    const float* __restrict__ bias, float* __restrict__ C,
    int M, int N, int K)
{
    constexpr int ASTR = 36, BSTR = 136;

    extern __shared__ float sm[];

    const int tid = threadIdx.x;
    const int wid = tid >> 5;
    const int lane = tid & 31;
    const int lr = lane >> 2;
    const int lc = lane & 3;
    const int wm = wid & 1;     // 2 m-tiles of 64
    const int wn = wid >> 1;    // 2 n-tiles of 64

    const int bm = blockIdx.y * 128;
    const int bn = blockIdx.x * 128;

    const uint32_t smem_base = (uint32_t)__cvta_generic_to_shared(sm);

    // issue one K-tile (128x32 A, 32x128 B) into stage s
    auto issue = [&](int k0, int s) {
        const uint32_t as_base = smem_base + (uint32_t)(s * GEMM_STAGE_FLOATS) * 4;
        const uint32_t bs_base = as_base + 128 * ASTR * 4;
        #pragma unroll
        for (int i = 0; i < 8; i++) {
            const int idx = tid + 128 * i;
            const int r = idx >> 3, c4 = idx & 7;
            cp16(as_base + (r * ASTR + c4 * 4) * 4,
                 A + (size_t)(bm + r) * K + k0 + c4 * 4);
        }
        #pragma unroll
        for (int i = 0; i < 8; i++) {
            const int idx = tid + 128 * i;
            const int r = idx >> 5, c4 = idx & 31;
            cp16(bs_base + (r * BSTR + c4 * 4) * 4,
                 B + (size_t)(k0 + r) * N + bn + c4 * 4);
        }
        asm volatile("cp.async.commit_group;\n" ::);
    };

    float acc[4][8][4] = {};   // [mi][ni][frag]

    const int niter = K / 32;
    issue(0, 0);
    if (niter > 1) issue(32, 1);

    for (int it = 0; it < niter; it++) {
        if (it < niter - 1)
            asm volatile("cp.async.wait_group 1;\n" ::);
        else
            asm volatile("cp.async.wait_group 0;\n" ::);
        __syncthreads();

        const float* As = sm + (it & 1) * GEMM_STAGE_FLOATS;
        const float* Bs = As + 128 * ASTR;

        #pragma unroll
        for (int ks = 0; ks < 4; ks++) {
            const int k = ks * 8;
            uint32_t afr[4][4];
            #pragma unroll
            for (int mi = 0; mi < 4; mi++) {
                const int r = wm * 64 + mi * 16;
                afr[mi][0] = __float_as_uint(As[(r + lr) * ASTR + k + lc]);
                afr[mi][1] = __float_as_uint(As[(r + 8 + lr) * ASTR + k + lc]);
                afr[mi][2] = __float_as_uint(As[(r + lr) * ASTR + k + 4 + lc]);
                afr[mi][3] = __float_as_uint(As[(r + 8 + lr) * ASTR + k + 4 + lc]);
            }
            uint32_t bfr[8][2];
            #pragma unroll
            for (int ni = 0; ni < 8; ni++) {
                const int c = wn * 64 + ni * 8 + lr;
                bfr[ni][0] = __float_as_uint(Bs[(k + lc) * BSTR + c]);
                bfr[ni][1] = __float_as_uint(Bs[(k + 4 + lc) * BSTR + c]);
            }
            #pragma unroll
            for (int mi = 0; mi < 4; mi++)
                #pragma unroll
                for (int ni = 0; ni < 8; ni++)
                    mma_tf32(acc[mi][ni], afr[mi], bfr[ni]);
        }
        __syncthreads();

        if (it + 2 < niter) issue((it + 2) * 32, it & 1);
    }

    // epilogue
    #pragma unroll
    for (int mi = 0; mi < 4; mi++) {
        #pragma unroll
        for (int ni = 0; ni < 8; ni++) {
            const int r0 = bm + wm * 64 + mi * 16 + lr;
            const int c0 = bn + wn * 64 + ni * 8 + lc * 2;
            float2 b01 = *(const float2*)(bias + c0);
            float2 v0 = make_float2(acc[mi][ni][0] + b01.x, acc[mi][ni][1] + b01.y);
            float2 v1 = make_float2(acc[mi][ni][2] + b01.x, acc[mi][ni][3] + b01.y);
            *(float2*)(C + (size_t)r0 * N + c0) = v0;
            *(float2*)(C + (size_t)(r0 + 8) * N + c0) = v1;
        }
    }
}

// ---------------------------------------------------------------------------
// comb[w][h][i][j] = mask[w][i][j] + bias_table[rel_index[i*49+j]][h]
// ---------------------------------------------------------------------------
__global__ __launch_bounds__(256) void comb_kernel(
    const float* __restrict__ mask, const float* __restrict__ bias_table,
    const int* __restrict__ rel_index, float* __restrict__ comb)
{
    const int total = NWIN * HEADS * NTOK * NTOK;
    int idx = blockIdx.x * 256 + threadIdx.x;
    if (idx < total) {
        const int ij = idx % (NTOK * NTOK);
        const int wh = idx / (NTOK * NTOK);
        const int h = wh & (HEADS - 1);
        const int w = wh >> 3;
        comb[idx] = mask[w * NTOK * NTOK + ij] + bias_table[rel_index[ij] * HEADS + h];
    }
}

// ---------------------------------------------------------------------------
// Register-resident-softmax bf16 attention (round-8 known good).
// ---------------------------------------------------------------------------
__global__ __launch_bounds__(128) void attn_reg_kernel(
    const float* __restrict__ qkv,       // [B, N, 768]
    const float* __restrict__ comb,      // [64][8][49][49]
    float* __restrict__ out)             // [B, N, 256] (tf32-rounded)
{
    __shared__ __align__(16) uint32_t sw[7104];
    uint32_t* Qh  = sw;            // 64 x 20
    uint32_t* Ql  = sw + 1280;
    uint32_t* Kh  = sw + 2560;     // 56 x 20
    uint32_t* Kl  = sw + 3680;
    uint32_t* Vth = sw + 4800;     // 32 x 36 (V transposed [d][j])
    uint32_t* Vtl = sw + 5952;

    const int b = blockIdx.x;
    const int h = blockIdx.y;
    const int tid = threadIdx.x;
    const int wid = tid >> 5;
    const int lane = tid & 31;
    const int lr = lane >> 2;
    const int lc = lane & 3;

    const float scale = 0.17677669529663687f;
    const float* base = qkv + (size_t)b * NTOK * 3 * DIM + h * HD;

    {
        __nv_bfloat16* vhH = (__nv_bfloat16*)Vth;
        __nv_bfloat16* vlH = (__nv_bfloat16*)Vtl;
        for (int e = tid; e < HD * 15; e += 128) {
            const int d = e / 15;
            const int j = NTOK + (e % 15);
            vhH[d * 72 + j] = __float2bfloat16(0.f);
            vlH[d * 72 + j] = __float2bfloat16(0.f);
        }
        for (int pe = tid; pe < NTOK * (HD / 2); pe += 128) {
            const int n = pe >> 4;
            const int dp = pe & 15;
            const int d = dp * 2;
            const float* row = base + (size_t)n * (3 * DIM) + d;
            float2 q2 = *(const float2*)(row);
            float2 k2 = *(const float2*)(row + DIM);
            float2 v2 = *(const float2*)(row + 2 * DIM);
            q2.x *= scale; q2.y *= scale;

            uint32_t hi, lo;
            split_pack_bf16(q2.x, q2.y, hi, lo);
            Qh[n * 20 + dp] = hi;
            Ql[n * 20 + dp] = lo;
            split_pack_bf16(k2.x, k2.y, hi, lo);
            Kh[n * 20 + dp] = hi;
            Kl[n * 20 + dp] = lo;

            __nv_bfloat16 vh0 = __float2bfloat16(v2.x);
            __nv_bfloat16 vh1 = __float2bfloat16(v2.y);
            __nv_bfloat16 vl0 = __float2bfloat16(v2.x - __bfloat162float(vh0));
            __nv_bfloat16 vl1 = __float2bfloat16(v2.y - __bfloat162float(vh1));
            vhH[d * 72 + n] = vh0;
            vhH[(d + 1) * 72 + n] = vh1;
            vlH[d * 72 + n] = vl0;
            vlH[(d + 1) * 72 + n] = vl1;
        }
    }
    __syncthreads();

    const int mr = wid * 16;

    float sacc[7][4] = {};
    #pragma unroll
    for (int kt = 0; kt < 2; kt++) {
        const int kw = kt * 8;
        uint32_t ah[4], al[4];
        ah[0] = Qh[(mr + lr) * 20 + kw + lc];
        ah[1] = Qh[(mr + 8 + lr) * 20 + kw + lc];
        ah[2] = Qh[(mr + lr) * 20 + kw + 4 + lc];
        ah[3] = Qh[(mr + 8 + lr) * 20 + kw + 4 + lc];
        al[0] = Ql[(mr + lr) * 20 + kw + lc];
        al[1] = Ql[(mr + 8 + lr) * 20 + kw + lc];
        al[2] = Ql[(mr + lr) * 20 + kw + 4 + lc];
        al[3] = Ql[(mr + 8 + lr) * 20 + kw + 4 + lc];

        #pragma unroll
        for (int nt = 0; nt < 7; nt++) {
            const int n0 = nt * 8;
            uint32_t bh[2], bl[2];
            bh[0] = Kh[(n0 + lr) * 20 + kw + lc];
            bh[1] = Kh[(n0 + lr) * 20 + kw + 4 + lc];
            bl[0] = Kl[(n0 + lr) * 20 + kw + lc];
            bl[1] = Kl[(n0 + lr) * 20 + kw + 4 + lc];
            mma_bf16(sacc[nt], ah, bh);
            mma_bf16(sacc[nt], al, bh);
            mma_bf16(sacc[nt], ah, bl);
        }
    }

    {
        const float* cb = comb + ((size_t)((b & (NWIN - 1)) * HEADS + h)) * (NTOK * NTOK);
        const int rA = mr + lr;
        const int rB = mr + 8 + lr;
        const bool okA = rA < NTOK;
        const bool okB = rB < NTOK;
        float mA = -CUDART_INF_F, mB = -CUDART_INF_F;

        #pragma unroll
        for (int nt = 0; nt < 7; nt++) {
            const int c0 = nt * 8 + 2 * lc;
            const bool ok0 = c0 < NTOK;
            const bool ok1 = (c0 + 1) < NTOK;
            float v0A = (okA && ok0) ? sacc[nt][0] + __ldg(cb + rA * NTOK + c0)     : -CUDART_INF_F;
            float v1A = (okA && ok1) ? sacc[nt][1] + __ldg(cb + rA * NTOK + c0 + 1) : -CUDART_INF_F;
            float v0B = (okB && ok0) ? sacc[nt][2] + __ldg(cb + rB * NTOK + c0)     : -CUDART_INF_F;
            float v1B = (okB && ok1) ? sacc[nt][3] + __ldg(cb + rB * NTOK + c0 + 1) : -CUDART_INF_F;
            sacc[nt][0] = v0A; sacc[nt][1] = v1A;
            sacc[nt][2] = v0B; sacc[nt][3] = v1B;
            mA = fmaxf(mA, fmaxf(v0A, v1A));
            mB = fmaxf(mB, fmaxf(v0B, v1B));
        }
        mA = fmaxf(mA, __shfl_xor_sync(0xffffffffu, mA, 1));
        mA = fmaxf(mA, __shfl_xor_sync(0xffffffffu, mA, 2));
        mB = fmaxf(mB, __shfl_xor_sync(0xffffffffu, mB, 1));
        mB = fmaxf(mB, __shfl_xor_sync(0xffffffffu, mB, 2));

        float sA = 0.f, sB = 0.f;
        #pragma unroll
        for (int nt = 0; nt < 7; nt++) {
            float e0A = __expf(sacc[nt][0] - mA);
            float e1A = __expf(sacc[nt][1] - mA);
            float e0B = __expf(sacc[nt][2] - mB);
            float e1B = __expf(sacc[nt][3] - mB);
            sacc[nt][0] = e0A; sacc[nt][1] = e1A;
            sacc[nt][2] = e0B; sacc[nt][3] = e1B;
            sA += e0A + e1A;
            sB += e0B + e1B;
        }
        sA += __shfl_xor_sync(0xffffffffu, sA, 1);
        sA += __shfl_xor_sync(0xffffffffu, sA, 2);
        sB += __shfl_xor_sync(0xffffffffu, sB, 1);
        sB += __shfl_xor_sync(0xffffffffu, sB, 2);
        const float invA = 1.f / sA;
        const float invB = 1.f / sB;
        #pragma unroll
        for (int nt = 0; nt < 7; nt++) {
            sacc[nt][0] *= invA; sacc[nt][1] *= invA;
            sacc[nt][2] *= invB; sacc[nt][3] *= invB;
        }
    }

    {
        float oacc[4][4] = {};
        #pragma unroll
        for (int kt = 0; kt < 4; kt++) {
            const int kw = kt * 8;
            const int t0 = 2 * kt;
            const int t1 = 2 * kt + 1;
            uint32_t ah[4], al[4];
            split_pack_bf16(sacc[t0][0], sacc[t0][1], ah[0], al[0]);
            split_pack_bf16(sacc[t0][2], sacc[t0][3], ah[1], al[1]);
            if (t1 < 7) {
                split_pack_bf16(sacc[t1][0], sacc[t1][1], ah[2], al[2]);
                split_pack_bf16(sacc[t1][2], sacc[t1][3], ah[3], al[3]);
            } else {
                ah[2] = ah[3] = al[2] = al[3] = 0u;
            }

            #pragma unroll
            for (int nt = 0; nt < 4; nt++) {
                const int n0 = nt * 8;
                uint32_t bh[2], bl[2];
                bh[0] = Vth[(n0 + lr) * 36 + kw + lc];
                bh[1] = Vth[(n0 + lr) * 36 + kw + 4 + lc];
                bl[0] = Vtl[(n0 + lr) * 36 + kw + lc];
                bl[1] = Vtl[(n0 + lr) * 36 + kw + 4 + lc];
                mma_bf16(oacc[nt], ah, bh);
                mma_bf16(oacc[nt], al, bh);
                mma_bf16(oacc[nt], ah, bl);
            }
        }

        const int r0 = mr + lr;
        const int r1 = mr + 8 + lr;
        #pragma unroll
        for (int nt = 0; nt < 4; nt++) {
            const int c0 = h * HD + nt * 8 + lc * 2;
            if (r0 < NTOK) {
                float2 v = make_float2(__uint_as_float(f2tf32(oacc[nt][0])),
                                       __uint_as_float(f2tf32(oacc[nt][1])));
                *(float2*)(out + ((size_t)b * NTOK + r0) * DIM + c0) = v;
            }
            if (r1 < NTOK) {
                float2 v = make_float2(__uint_as_float(f2tf32(oacc[nt][2])),
                                       __uint_as_float(f2tf32(oacc[nt][3])));
                *(float2*)(out + ((size_t)b * NTOK + r1) * DIM + c0) = v;
            }
        }
    }
}

// ---------------------------------------------------------------------------
extern "C" void kernel_launch(void* const* d_in, const int* in_sizes, int n_in,
                              void* d_out, int out_size)
{
    const float* x          = (const float*)d_in[0];
    const float* mask       = (const float*)d_in[1];
    const float* qkv_w      = (const float*)d_in[2];
    const float* qkv_b      = (const float*)d_in[3];
    const float* proj_w     = (const float*)d_in[4];
    const float* proj_b     = (const float*)d_in[5];
    const float* bias_table = (const float*)d_in[6];
    const int*   rel_index  = (const int*)d_in[7];
    float* out = (float*)d_out;

    float *xt_buf, *qkv_buf, *ao_buf, *wq_buf, *wp_buf, *comb_buf;
    cudaGetSymbolAddress((void**)&xt_buf, g_xt);
    cudaGetSymbolAddress((void**)&qkv_buf, g_qkv);
    cudaGetSymbolAddress((void**)&ao_buf, g_ao);
    cudaGetSymbolAddress((void**)&wq_buf, g_wq);
    cudaGetSymbolAddress((void**)&wp_buf, g_wp);
    cudaGetSymbolAddress((void**)&comb_buf, g_comb);

    static bool attr_set = false;
    if (!attr_set) {
        cudaFuncSetAttribute(gemm_tf32_w64,
                             cudaFuncAttributeMaxDynamicSharedMemorySize,
                             GEMM_SMEM_BYTES);
        attr_set = true;
    }

    const int M = BATCH * NTOK;   // 100352 = 128 * 784

    // 0a) tf32-round x and weights
    {
        const int n4x = M * DIM / 4;
        cvt_tf32_kernel<<<2048, 256>>>((const float4*)x, (float4*)xt_buf, n4x);
        cvt_tf32_kernel<<<192, 256>>>((const float4*)qkv_w, (float4*)wq_buf,
                                      DIM * 3 * DIM / 4);
        cvt_tf32_kernel<<<64, 256>>>((const float4*)proj_w, (float4*)wp_buf,
                                     DIM * DIM / 4);
    }
    // 0b) combined bias+mask table
    {
        const int total = NWIN * HEADS * NTOK * NTOK;
        comb_kernel<<<(total + 255) / 256, 256>>>(mask, bias_table, rel_index, comb_buf);
    }
    // 1) QKV GEMM: [M,256] @ [256,768] + b
    {
        dim3 grid(3 * DIM / 128, M / 128);
        gemm_tf32_w64<<<grid, 128, GEMM_SMEM_BYTES>>>(xt_buf, wq_buf, qkv_b, qkv_buf,
                                                      M, 3 * DIM, DIM);
    }
    // 2) register-softmax attention
    {
        dim3 grid(BATCH, HEADS);
        attn_reg_kernel<<<grid, 128>>>(qkv_buf, comb_buf, ao_buf);
    }
    // 3) Proj GEMM
    {
        dim3 grid(DIM / 128, M / 128);
        gemm_tf32_w64<<<grid, 128, GEMM_SMEM_BYTES>>>(ao_buf, wp_buf, proj_b, out,
                                                      M, DIM, DIM);
    }
}

// round 11
// speedup vs baseline: 2.1057x; 1.0375x over previous
#include <cuda_runtime.h>
#include <cuda_bf16.h>
#include <cstdint>
#include <math_constants.h>

#define HEADS 8
#define HD 32
#define NTOK 49
#define DIM 256
#define BATCH 2048
#define NWIN 64

// scratch (allocation-free rule: device globals)
__device__ float g_qkv[(size_t)BATCH * NTOK * 3 * DIM];      // [B, N, 768]
__device__ float g_ao[(size_t)BATCH * NTOK * DIM];           // attention out (tf32-rounded)
__device__ float g_wq[DIM * 3 * DIM];                        // tf32(qkv_w)
__device__ float g_wp[DIM * DIM];                            // tf32(proj_w)
__device__ float g_comb[(size_t)NWIN * HEADS * NTOK * NTOK]; // [w][h][i][j]

__device__ __forceinline__ uint32_t f2tf32(float x) {
    uint32_t u;
    asm("cvt.rna.tf32.f32 %0, %1;" : "=r"(u) : "f"(x));
    return u;
}

__device__ __forceinline__ void mma_tf32(float* c, const uint32_t* a, const uint32_t* b) {
    asm volatile(
        "mma.sync.aligned.m16n8k8.row.col.f32.tf32.tf32.f32 "
        "{%0,%1,%2,%3}, {%4,%5,%6,%7}, {%8,%9}, {%0,%1,%2,%3};"
        : "+f"(c[0]), "+f"(c[1]), "+f"(c[2]), "+f"(c[3])
        : "r"(a[0]), "r"(a[1]), "r"(a[2]), "r"(a[3]), "r"(b[0]), "r"(b[1]));
}

__device__ __forceinline__ void mma_bf16(float* c, const uint32_t* a, const uint32_t* b) {
    asm volatile(
        "mma.sync.aligned.m16n8k16.row.col.f32.bf16.bf16.f32 "
        "{%0,%1,%2,%3}, {%4,%5,%6,%7}, {%8,%9}, {%0,%1,%2,%3};"
        : "+f"(c[0]), "+f"(c[1]), "+f"(c[2]), "+f"(c[3])
        : "r"(a[0]), "r"(a[1]), "r"(a[2]), "r"(a[3]), "r"(b[0]), "r"(b[1]));
}

__device__ __forceinline__ void split_pack_bf16(float x, float y,
                                                uint32_t& hi, uint32_t& lo) {
    __nv_bfloat16 hx = __float2bfloat16(x);
    __nv_bfloat16 hy = __float2bfloat16(y);
    __nv_bfloat16 lx = __float2bfloat16(x - __bfloat162float(hx));
    __nv_bfloat16 ly = __float2bfloat16(y - __bfloat162float(hy));
    __nv_bfloat162 h; h.x = hx; h.y = hy;
    __nv_bfloat162 l; l.x = lx; l.y = ly;
    hi = *(uint32_t*)&h;
    lo = *(uint32_t*)&l;
}

__device__ __forceinline__ void cp16(uint32_t smem_dst, const void* gptr) {
    asm volatile("cp.async.cg.shared.global [%0], [%1], 16;\n"
                 :: "r"(smem_dst), "l"(gptr));
}

// ---------------------------------------------------------------------------
// Elementwise tf32 rounding pass (weights only now)
// ---------------------------------------------------------------------------
__global__ __launch_bounds__(256) void cvt_tf32_kernel(
    const float4* __restrict__ src, float4* __restrict__ dst, int n4)
{
    for (int i = blockIdx.x * 256 + threadIdx.x; i < n4; i += gridDim.x * 256) {
        float4 v = src[i];
        float4 o;
        o.x = __uint_as_float(f2tf32(v.x));
        o.y = __uint_as_float(f2tf32(v.y));
        o.z = __uint_as_float(f2tf32(v.z));
        o.w = __uint_as_float(f2tf32(v.w));
        dst[i] = o;
    }
}

// ---------------------------------------------------------------------------
// TF32 mma.sync GEMM, cp.async double-buffered, 64x64 warp tiles.
// BM=128, BN=128, BK=32, 128 threads (4 warps 2x2).
// CVT_A: apply cvt.rna.tf32 to A-fragments (A loaded raw f32).
// ---------------------------------------------------------------------------
#define GEMM_STAGE_FLOATS (128 * 36 + 32 * 136)
#define GEMM_SMEM_BYTES (2 * GEMM_STAGE_FLOATS * 4)

template<bool CVT_A>
__global__ __launch_bounds__(128) void gemm_tf32_w64(
    const float* __restrict__ A, const float* __restrict__ B,
    const float* __restrict__ bias, float* __restrict__ C,
    int M, int N, int K)
{
    constexpr int ASTR = 36, BSTR = 136;

    extern __shared__ float sm[];

    const int tid = threadIdx.x;
    const int wid = tid >> 5;
    const int lane = tid & 31;
    const int lr = lane >> 2;
    const int lc = lane & 3;
    const int wm = wid & 1;     // 2 m-tiles of 64
    const int wn = wid >> 1;    // 2 n-tiles of 64

    const int bm = blockIdx.y * 128;
    const int bn = blockIdx.x * 128;

    const uint32_t smem_base = (uint32_t)__cvta_generic_to_shared(sm);

    // issue one K-tile (128x32 A, 32x128 B) into stage s
    auto issue = [&](int k0, int s) {
        const uint32_t as_base = smem_base + (uint32_t)(s * GEMM_STAGE_FLOATS) * 4;
        const uint32_t bs_base = as_base + 128 * ASTR * 4;
        #pragma unroll
        for (int i = 0; i < 8; i++) {
            const int idx = tid + 128 * i;
            const int r = idx >> 3, c4 = idx & 7;
            cp16(as_base + (r * ASTR + c4 * 4) * 4,
                 A + (size_t)(bm + r) * K + k0 + c4 * 4);
        }
        #pragma unroll
        for (int i = 0; i < 8; i++) {
            const int idx = tid + 128 * i;
            const int r = idx >> 5, c4 = idx & 31;
            cp16(bs_base + (r * BSTR + c4 * 4) * 4,
                 B + (size_t)(k0 + r) * N + bn + c4 * 4);
        }
        asm volatile("cp.async.commit_group;\n" ::);
    };

    float acc[4][8][4] = {};   // [mi][ni][frag]

    const int niter = K / 32;
    issue(0, 0);
    if (niter > 1) issue(32, 1);

    for (int it = 0; it < niter; it++) {
        if (it < niter - 1)
            asm volatile("cp.async.wait_group 1;\n" ::);
        else
            asm volatile("cp.async.wait_group 0;\n" ::);
        __syncthreads();

        const float* As = sm + (it & 1) * GEMM_STAGE_FLOATS;
        const float* Bs = As + 128 * ASTR;

        #pragma unroll
        for (int ks = 0; ks < 4; ks++) {
            const int k = ks * 8;
            uint32_t afr[4][4];
            #pragma unroll
            for (int mi = 0; mi < 4; mi++) {
                const int r = wm * 64 + mi * 16;
                if (CVT_A) {
                    afr[mi][0] = f2tf32(As[(r + lr) * ASTR + k + lc]);
                    afr[mi][1] = f2tf32(As[(r + 8 + lr) * ASTR + k + lc]);
                    afr[mi][2] = f2tf32(As[(r + lr) * ASTR + k + 4 + lc]);
                    afr[mi][3] = f2tf32(As[(r + 8 + lr) * ASTR + k + 4 + lc]);
                } else {
                    afr[mi][0] = __float_as_uint(As[(r + lr) * ASTR + k + lc]);
                    afr[mi][1] = __float_as_uint(As[(r + 8 + lr) * ASTR + k + lc]);
                    afr[mi][2] = __float_as_uint(As[(r + lr) * ASTR + k + 4 + lc]);
                    afr[mi][3] = __float_as_uint(As[(r + 8 + lr) * ASTR + k + 4 + lc]);
                }
            }
            uint32_t bfr[8][2];
            #pragma unroll
            for (int ni = 0; ni < 8; ni++) {
                const int c = wn * 64 + ni * 8 + lr;
                bfr[ni][0] = __float_as_uint(Bs[(k + lc) * BSTR + c]);
                bfr[ni][1] = __float_as_uint(Bs[(k + 4 + lc) * BSTR + c]);
            }
            #pragma unroll
            for (int mi = 0; mi < 4; mi++)
                #pragma unroll
                for (int ni = 0; ni < 8; ni++)
                    mma_tf32(acc[mi][ni], afr[mi], bfr[ni]);
        }
        __syncthreads();

        if (it + 2 < niter) issue((it + 2) * 32, it & 1);
    }

    // epilogue
    #pragma unroll
    for (int mi = 0; mi < 4; mi++) {
        #pragma unroll
        for (int ni = 0; ni < 8; ni++) {
            const int r0 = bm + wm * 64 + mi * 16 + lr;
            const int c0 = bn + wn * 64 + ni * 8 + lc * 2;
            float2 b01 = *(const float2*)(bias + c0);
            float2 v0 = make_float2(acc[mi][ni][0] + b01.x, acc[mi][ni][1] + b01.y);
            float2 v1 = make_float2(acc[mi][ni][2] + b01.x, acc[mi][ni][3] + b01.y);
            *(float2*)(C + (size_t)r0 * N + c0) = v0;
            *(float2*)(C + (size_t)(r0 + 8) * N + c0) = v1;
        }
    }
}

// ---------------------------------------------------------------------------
// comb[w][h][i][j] = mask[w][i][j] + bias_table[rel_index[i*49+j]][h]
// ---------------------------------------------------------------------------
__global__ __launch_bounds__(256) void comb_kernel(
    const float* __restrict__ mask, const float* __restrict__ bias_table,
    const int* __restrict__ rel_index, float* __restrict__ comb)
{
    const int total = NWIN * HEADS * NTOK * NTOK;
    int idx = blockIdx.x * 256 + threadIdx.x;
    if (idx < total) {
        const int ij = idx % (NTOK * NTOK);
        const int wh = idx / (NTOK * NTOK);
        const int h = wh & (HEADS - 1);
        const int w = wh >> 3;
        comb[idx] = mask[w * NTOK * NTOK + ij] + bias_table[rel_index[ij] * HEADS + h];
    }
}

// ---------------------------------------------------------------------------
// Register-resident-softmax bf16 attention (round-8 known good).
// ---------------------------------------------------------------------------
__global__ __launch_bounds__(128) void attn_reg_kernel(
    const float* __restrict__ qkv,       // [B, N, 768]
    const float* __restrict__ comb,      // [64][8][49][49]
    float* __restrict__ out)             // [B, N, 256] (tf32-rounded)
{
    __shared__ __align__(16) uint32_t sw[7104];
    uint32_t* Qh  = sw;            // 64 x 20
    uint32_t* Ql  = sw + 1280;
    uint32_t* Kh  = sw + 2560;     // 56 x 20
    uint32_t* Kl  = sw + 3680;
    uint32_t* Vth = sw + 4800;     // 32 x 36 (V transposed [d][j])
    uint32_t* Vtl = sw + 5952;

    const int b = blockIdx.x;
    const int h = blockIdx.y;
    const int tid = threadIdx.x;
    const int wid = tid >> 5;
    const int lane = tid & 31;
    const int lr = lane >> 2;
    const int lc = lane & 3;

    const float scale = 0.17677669529663687f;
    const float* base = qkv + (size_t)b * NTOK * 3 * DIM + h * HD;

    {
        __nv_bfloat16* vhH = (__nv_bfloat16*)Vth;
        __nv_bfloat16* vlH = (__nv_bfloat16*)Vtl;
        for (int e = tid; e < HD * 15; e += 128) {
            const int d = e / 15;
            const int j = NTOK + (e % 15);
            vhH[d * 72 + j] = __float2bfloat16(0.f);
            vlH[d * 72 + j] = __float2bfloat16(0.f);
        }
        for (int pe = tid; pe < NTOK * (HD / 2); pe += 128) {
            const int n = pe >> 4;
            const int dp = pe & 15;
            const int d = dp * 2;
            const float* row = base + (size_t)n * (3 * DIM) + d;
            float2 q2 = *(const float2*)(row);
            float2 k2 = *(const float2*)(row + DIM);
            float2 v2 = *(const float2*)(row + 2 * DIM);
            q2.x *= scale; q2.y *= scale;

            uint32_t hi, lo;
            split_pack_bf16(q2.x, q2.y, hi, lo);
            Qh[n * 20 + dp] = hi;
            Ql[n * 20 + dp] = lo;
            split_pack_bf16(k2.x, k2.y, hi, lo);
            Kh[n * 20 + dp] = hi;
            Kl[n * 20 + dp] = lo;

            __nv_bfloat16 vh0 = __float2bfloat16(v2.x);
            __nv_bfloat16 vh1 = __float2bfloat16(v2.y);
            __nv_bfloat16 vl0 = __float2bfloat16(v2.x - __bfloat162float(vh0));
            __nv_bfloat16 vl1 = __float2bfloat16(v2.y - __bfloat162float(vh1));
            vhH[d * 72 + n] = vh0;
            vhH[(d + 1) * 72 + n] = vh1;
            vlH[d * 72 + n] = vl0;
            vlH[(d + 1) * 72 + n] = vl1;
        }
    }
    __syncthreads();

    const int mr = wid * 16;

    float sacc[7][4] = {};
    #pragma unroll
    for (int kt = 0; kt < 2; kt++) {
        const int kw = kt * 8;
        uint32_t ah[4], al[4];
        ah[0] = Qh[(mr + lr) * 20 + kw + lc];
        ah[1] = Qh[(mr + 8 + lr) * 20 + kw + lc];
        ah[2] = Qh[(mr + lr) * 20 + kw + 4 + lc];
        ah[3] = Qh[(mr + 8 + lr) * 20 + kw + 4 + lc];
        al[0] = Ql[(mr + lr) * 20 + kw + lc];
        al[1] = Ql[(mr + 8 + lr) * 20 + kw + lc];
        al[2] = Ql[(mr + lr) * 20 + kw + 4 + lc];
        al[3] = Ql[(mr + 8 + lr) * 20 + kw + 4 + lc];

        #pragma unroll
        for (int nt = 0; nt < 7; nt++) {
            const int n0 = nt * 8;
            uint32_t bh[2], bl[2];
            bh[0] = Kh[(n0 + lr) * 20 + kw + lc];
            bh[1] = Kh[(n0 + lr) * 20 + kw + 4 + lc];
            bl[0] = Kl[(n0 + lr) * 20 + kw + lc];
            bl[1] = Kl[(n0 + lr) * 20 + kw + 4 + lc];
            mma_bf16(sacc[nt], ah, bh);
            mma_bf16(sacc[nt], al, bh);
            mma_bf16(sacc[nt], ah, bl);
        }
    }

    {
        const float* cb = comb + ((size_t)((b & (NWIN - 1)) * HEADS + h)) * (NTOK * NTOK);
        const int rA = mr + lr;
        const int rB = mr + 8 + lr;
        const bool okA = rA < NTOK;
        const bool okB = rB < NTOK;
        float mA = -CUDART_INF_F, mB = -CUDART_INF_F;

        #pragma unroll
        for (int nt = 0; nt < 7; nt++) {
            const int c0 = nt * 8 + 2 * lc;
            const bool ok0 = c0 < NTOK;
            const bool ok1 = (c0 + 1) < NTOK;
            float v0A = (okA && ok0) ? sacc[nt][0] + __ldg(cb + rA * NTOK + c0)     : -CUDART_INF_F;
            float v1A = (okA && ok1) ? sacc[nt][1] + __ldg(cb + rA * NTOK + c0 + 1) : -CUDART_INF_F;
            float v0B = (okB && ok0) ? sacc[nt][2] + __ldg(cb + rB * NTOK + c0)     : -CUDART_INF_F;
            float v1B = (okB && ok1) ? sacc[nt][3] + __ldg(cb + rB * NTOK + c0 + 1) : -CUDART_INF_F;
            sacc[nt][0] = v0A; sacc[nt][1] = v1A;
            sacc[nt][2] = v0B; sacc[nt][3] = v1B;
            mA = fmaxf(mA, fmaxf(v0A, v1A));
            mB = fmaxf(mB, fmaxf(v0B, v1B));
        }
        mA = fmaxf(mA, __shfl_xor_sync(0xffffffffu, mA, 1));
        mA = fmaxf(mA, __shfl_xor_sync(0xffffffffu, mA, 2));
        mB = fmaxf(mB, __shfl_xor_sync(0xffffffffu, mB, 1));
        mB = fmaxf(mB, __shfl_xor_sync(0xffffffffu, mB, 2));

        float sA = 0.f, sB = 0.f;
        #pragma unroll
        for (int nt = 0; nt < 7; nt++) {
            float e0A = __expf(sacc[nt][0] - mA);
            float e1A = __expf(sacc[nt][1] - mA);
            float e0B = __expf(sacc[nt][2] - mB);
            float e1B = __expf(sacc[nt][3] - mB);
            sacc[nt][0] = e0A; sacc[nt][1] = e1A;
            sacc[nt][2] = e0B; sacc[nt][3] = e1B;
            sA += e0A + e1A;
            sB += e0B + e1B;
        }
        sA += __shfl_xor_sync(0xffffffffu, sA, 1);
        sA += __shfl_xor_sync(0xffffffffu, sA, 2);
        sB += __shfl_xor_sync(0xffffffffu, sB, 1);
        sB += __shfl_xor_sync(0xffffffffu, sB, 2);
        const float invA = 1.f / sA;
        const float invB = 1.f / sB;
        #pragma unroll
        for (int nt = 0; nt < 7; nt++) {
            sacc[nt][0] *= invA; sacc[nt][1] *= invA;
            sacc[nt][2] *= invB; sacc[nt][3] *= invB;
        }
    }

    {
        float oacc[4][4] = {};
        #pragma unroll
        for (int kt = 0; kt < 4; kt++) {
            const int kw = kt * 8;
            const int t0 = 2 * kt;
            const int t1 = 2 * kt + 1;
            uint32_t ah[4], al[4];
            split_pack_bf16(sacc[t0][0], sacc[t0][1], ah[0], al[0]);
            split_pack_bf16(sacc[t0][2], sacc[t0][3], ah[1], al[1]);
            if (t1 < 7) {
                split_pack_bf16(sacc[t1][0], sacc[t1][1], ah[2], al[2]);
                split_pack_bf16(sacc[t1][2], sacc[t1][3], ah[3], al[3]);
            } else {
                ah[2] = ah[3] = al[2] = al[3] = 0u;
            }

            #pragma unroll
            for (int nt = 0; nt < 4; nt++) {
                const int n0 = nt * 8;
                uint32_t bh[2], bl[2];
                bh[0] = Vth[(n0 + lr) * 36 + kw + lc];
                bh[1] = Vth[(n0 + lr) * 36 + kw + 4 + lc];
                bl[0] = Vtl[(n0 + lr) * 36 + kw + lc];
                bl[1] = Vtl[(n0 + lr) * 36 + kw + 4 + lc];
                mma_bf16(oacc[nt], ah, bh);
                mma_bf16(oacc[nt], al, bh);
                mma_bf16(oacc[nt], ah, bl);
            }
        }

        const int r0 = mr + lr;
        const int r1 = mr + 8 + lr;
        #pragma unroll
        for (int nt = 0; nt < 4; nt++) {
            const int c0 = h * HD + nt * 8 + lc * 2;
            if (r0 < NTOK) {
                float2 v = make_float2(__uint_as_float(f2tf32(oacc[nt][0])),
                                       __uint_as_float(f2tf32(oacc[nt][1])));
                *(float2*)(out + ((size_t)b * NTOK + r0) * DIM + c0) = v;
            }
            if (r1 < NTOK) {
                float2 v = make_float2(__uint_as_float(f2tf32(oacc[nt][2])),
                                       __uint_as_float(f2tf32(oacc[nt][3])));
                *(float2*)(out + ((size_t)b * NTOK + r1) * DIM + c0) = v;
            }
        }
    }
}

// ---------------------------------------------------------------------------
extern "C" void kernel_launch(void* const* d_in, const int* in_sizes, int n_in,
                              void* d_out, int out_size)
{
    const float* x          = (const float*)d_in[0];
    const float* mask       = (const float*)d_in[1];
    const float* qkv_w      = (const float*)d_in[2];
    const float* qkv_b      = (const float*)d_in[3];
    const float* proj_w     = (const float*)d_in[4];
    const float* proj_b     = (const float*)d_in[5];
    const float* bias_table = (const float*)d_in[6];
    const int*   rel_index  = (const int*)d_in[7];
    float* out = (float*)d_out;

    float *qkv_buf, *ao_buf, *wq_buf, *wp_buf, *comb_buf;
    cudaGetSymbolAddress((void**)&qkv_buf, g_qkv);
    cudaGetSymbolAddress((void**)&ao_buf, g_ao);
    cudaGetSymbolAddress((void**)&wq_buf, g_wq);
    cudaGetSymbolAddress((void**)&wp_buf, g_wp);
    cudaGetSymbolAddress((void**)&comb_buf, g_comb);

    static bool attr_set = false;
    if (!attr_set) {
        cudaFuncSetAttribute(gemm_tf32_w64<true>,
                             cudaFuncAttributeMaxDynamicSharedMemorySize,
                             GEMM_SMEM_BYTES);
        cudaFuncSetAttribute(gemm_tf32_w64<false>,
                             cudaFuncAttributeMaxDynamicSharedMemorySize,
                             GEMM_SMEM_BYTES);
        attr_set = true;
    }

    const int M = BATCH * NTOK;   // 100352 = 128 * 784

    // 0a) tf32-round weights (small)
    {
        cvt_tf32_kernel<<<192, 256>>>((const float4*)qkv_w, (float4*)wq_buf,
                                      DIM * 3 * DIM / 4);
        cvt_tf32_kernel<<<64, 256>>>((const float4*)proj_w, (float4*)wp_buf,
                                     DIM * DIM / 4);
    }
    // 0b) combined bias+mask table
    {
        const int total = NWIN * HEADS * NTOK * NTOK;
        comb_kernel<<<(total + 255) / 256, 256>>>(mask, bias_table, rel_index, comb_buf);
    }
    // 1) QKV GEMM: raw f32 x, cvt in A-frag path
    {
        dim3 grid(3 * DIM / 128, M / 128);
        gemm_tf32_w64<true><<<grid, 128, GEMM_SMEM_BYTES>>>(x, wq_buf, qkv_b, qkv_buf,
                                                            M, 3 * DIM, DIM);
    }
    // 2) register-softmax attention (emits tf32-rounded output)
    {
        dim3 grid(BATCH, HEADS);
        attn_reg_kernel<<<grid, 128>>>(qkv_buf, comb_buf, ao_buf);
    }
    // 3) Proj GEMM: A already tf32-rounded
    {
        dim3 grid(DIM / 128, M / 128);
        gemm_tf32_w64<false><<<grid, 128, GEMM_SMEM_BYTES>>>(ao_buf, wp_buf, proj_b, out,
                                                             M, DIM, DIM);
    }
}